// round 10
// baseline (speedup 1.0000x reference)
#include <cuda_runtime.h>
#include <cuda_fp16.h>
#include <cstdint>

#define BATCH   16
#define DIM     256
#define HWSZ    4096
#define NROWS   65536
#define NCODE   1024
#define XELEMS  16777216
#define ENCELEMS 67108864
#define MARGIN  4e-3f
#define MAXCAND 32
#define CT      576          // codes handled by tensor filter (9 tiles of 64)
#define CF_T    7            // fma code-tiles of 64 (codes 576..1023)

typedef unsigned long long u64;

// ---------------- scratch (device globals) ----------------
__device__ int      g_idx[NROWS];
__device__ int      g_hist[NCODE];
__device__ float    g_cbsq[NCODE];
__device__ float    g_insq[NROWS];
__device__ double   g_losssum;
__device__ float    g_xt[NROWS * 256];    // transposed x, fp32 [n][d]
__device__ uint32_t g_ahi[NROWS * 128];   // fp16x2 pairs, [n][d/2]
__device__ uint32_t g_bf[NCODE * 128];    // codebook fp16, MMA B-fragment order (64-wide tiles)

// ---------------- PTX helpers ----------------
__device__ __forceinline__ uint32_t smem_u32(const void* p) {
    uint32_t a;
    asm("{ .reg .u64 t; cvta.to.shared.u64 t, %1; cvt.u32.u64 %0, t; }" : "=r"(a) : "l"(p));
    return a;
}
#define LDSM4(r0, r1, r2, r3, a) \
    asm volatile("ldmatrix.sync.aligned.m8n8.x4.shared.b16 {%0,%1,%2,%3}, [%4];" \
        : "=r"(r0), "=r"(r1), "=r"(r2), "=r"(r3) : "r"(a))
#define MMA16816(d, a0, a1, a2, a3, b0, b1) \
    asm volatile("mma.sync.aligned.m16n8k16.row.col.f32.f16.f16.f32 " \
        "{%0,%1,%2,%3}, {%4,%5,%6,%7}, {%8,%9}, {%0,%1,%2,%3};" \
        : "+f"((d)[0]), "+f"((d)[1]), "+f"((d)[2]), "+f"((d)[3]) \
        : "r"(a0), "r"(a1), "r"(a2), "r"(a3), "r"(b0), "r"(b1))
#define CP_ASYNC16(dst, src) \
    asm volatile("cp.async.cg.shared.global [%0], [%1], 16;" :: "r"(dst), "l"(src))
#define CP_COMMIT() asm volatile("cp.async.commit_group;" ::: "memory")
#define CP_WAIT0()  asm volatile("cp.async.wait_group 0;" ::: "memory")
#define BAR1_256()  asm volatile("bar.sync 1, 256;" ::: "memory")

__device__ __forceinline__ u64 pack2(float lo, float hi) {
    u64 r;
    asm("mov.b64 %0, {%1, %2};" : "=l"(r) : "f"(lo), "f"(hi));
    return r;
}
__device__ __forceinline__ void unpack2(u64 v, float& lo, float& hi) {
    asm("mov.b64 {%0, %1}, %2;" : "=f"(lo), "=f"(hi) : "l"(v));
}
__device__ __forceinline__ void fma2(u64& acc, u64 a, u64 b) {
    asm("fma.rn.f32x2 %0, %1, %2, %0;" : "+l"(acc) : "l"(a), "l"(b));
}

// ---------------- SMEM layout for k_dist (dynamic) ----------------
#define SM_AHI    0          // 65536: A_hi resident, 4 tiles of [128][64 fp16]
#define SM_SX     65536      // 16*132*4 = 8448 (fma x stage)
#define SM_SCB    73984      // 16*68*4 = 4352 (fma cb stage)
#define SM_CBSQ   78336      // 4096
#define SM_INSQ   82432      // 512
#define SM_ROWMIN 82944      // 512
#define SM_CNT    83456      // 512
#define SM_CAND   83968      // 128*32*4 = 16384
#define SM_RED    100352     // 128*17*8 = 17408 (fma reduction)
#define SM_KEYQ   117760     // 5*128*8 = 5120
#define SM_TOTAL  122880

// ---------------- small kernels ----------------
__global__ void k_zero() {
    int t = blockIdx.x * blockDim.x + threadIdx.x;
    if (t == 0) g_losssum = 0.0;
    if (t < NCODE) g_hist[t] = 0;
}

// codebook -> fp16 B-fragment order (64-wide n-tiles) + per-code squared norms
// m16n8k16 .row.col B fragment: lane holds B[k=2*(lane&3)+{0,1}][n=lane>>2] in
// word0, +8 in k for word1. u32 idx = (((nt64*16+kstep)*8+n8g)*32+lane)*2+word.
__global__ void k_prep(const float* __restrict__ cb) {
    int i = blockIdx.x * 256 + threadIdx.x;      // over NCODE*128 u32 (d-pairs)
    int k = i >> 7;
    int d = (i & 127) * 2;
    float2 v = *reinterpret_cast<const float2*>(cb + (size_t)k * DIM + d);
    __half h0 = __float2half_rn(v.x);
    __half h1 = __float2half_rn(v.y);
    int nt64 = k >> 6, cc = k & 63;
    int n8g = cc >> 3;
    int lane = ((cc & 7) << 2) | ((d & 7) >> 1);
    int kstep = d >> 4;
    int word = (d >> 3) & 1;
    uint32_t idx = (uint32_t)((((nt64 * 16 + kstep) * 8 + n8g) * 32 + lane) * 2 + word);
    g_bf[idx] = ((uint32_t)__half_as_ushort(h1) << 16) | __half_as_ushort(h0);
    if (i < NCODE) {
        const float4* p = reinterpret_cast<const float4*>(cb + (size_t)i * DIM);
        float s = 0.f;
        #pragma unroll 8
        for (int dd = 0; dd < DIM / 4; dd++) {
            float4 q = p[dd];
            s += q.x * q.x; s += q.y * q.y; s += q.z * q.z; s += q.w * q.w;
        }
        g_cbsq[i] = s;
    }
}

// x NCHW -> a_hi [n][d] fp16x2 + g_xt fp32 + per-row |x|^2 (sequential-d)
__global__ void __launch_bounds__(256) k_split_x(const float* __restrict__ x) {
    __shared__ float s[256 * 33];
    const int t  = threadIdx.x;
    const int n0 = blockIdx.x * 32;
    const int b  = n0 >> 12;
    const int hw0 = n0 & 4095;
    const float* xb = x + (size_t)b * DIM * HWSZ + hw0;

    #pragma unroll
    for (int i = 0; i < 32; i++) {
        int lin = i * 256 + t;
        int d = lin >> 5, hw = lin & 31;
        s[d * 33 + hw] = xb[(size_t)d * HWSZ + hw];
    }
    __syncthreads();

    if (t < 32) {
        float acc = 0.f;
        #pragma unroll 8
        for (int d = 0; d < 256; d++) {
            float v = s[d * 33 + t];
            acc += v * v;
        }
        g_insq[n0 + t] = acc;
    }

    #pragma unroll
    for (int j = 0; j < 16; j++) {
        int lin = j * 256 + t;
        int nl = lin >> 7, c = lin & 127;
        float v0 = s[(2 * c) * 33 + nl];
        float v1 = s[(2 * c + 1) * 33 + nl];
        __half h0 = __float2half_rn(v0);
        __half h1 = __float2half_rn(v1);
        size_t o = (size_t)(n0 + nl) * 128 + c;
        g_ahi[o] = ((uint32_t)__half_as_ushort(h1) << 16) | __half_as_ushort(h0);
        float2* xt = reinterpret_cast<float2*>(&g_xt[(size_t)(n0 + nl) * 256 + 2 * c]);
        *xt = make_float2(v0, v1);
    }
}

// ---------------- hybrid tensor+fma distance/argmin kernel ----------------
// Warps 0..7:  HMMA filter over codes [0, CT) + candidate append (tensor pipe)
// Warps 8..15: exact fp32 f32x2 distances over codes [CT, 1024) (fma pipe)
// Then all threads rescore tensor candidates exactly; merge = global argmin.
__global__ void __launch_bounds__(512, 1) k_dist(const float* __restrict__ cb) {
    extern __shared__ __align__(1024) char smem[];
    const uint32_t sb = smem_u32(smem);
    const int t    = threadIdx.x;
    const int lane = t & 31;
    const int wid  = t >> 5;
    const int n0   = blockIdx.x * 128;

    float* s_sx   = reinterpret_cast<float*>(smem + SM_SX);
    float* s_scb  = reinterpret_cast<float*>(smem + SM_SCB);
    float* s_cbsq = reinterpret_cast<float*>(smem + SM_CBSQ);
    float* s_insq = reinterpret_cast<float*>(smem + SM_INSQ);
    uint32_t* s_rowmin = reinterpret_cast<uint32_t*>(smem + SM_ROWMIN);
    int* s_cnt = reinterpret_cast<int*>(smem + SM_CNT);
    uint32_t* s_cand = reinterpret_cast<uint32_t*>(smem + SM_CAND);
    u64* s_red  = reinterpret_cast<u64*>(smem + SM_RED);
    u64* s_keyq = reinterpret_cast<u64*>(smem + SM_KEYQ);

    s_cbsq[t] = g_cbsq[t];
    s_cbsq[t + 512] = g_cbsq[t + 512];
    if (t < 128) {
        s_insq[t] = g_insq[n0 + t];
        s_rowmin[t] = 0x7F800000u;   // +inf
        s_cnt[t] = 0;
    }

    // A_hi resident via cp.async (4096 16B segments; 8 per thread)
    #pragma unroll
    for (int i = 0; i < 8; i++) {
        int s = i * 512 + t;
        int q = s >> 10, rem = s & 1023;
        int row = rem >> 3, j = rem & 7;
        uint32_t dst = sb + SM_AHI + q * 16384 + row * 128 +
                       ((j * 16) ^ ((row & 7) << 4));
        const uint32_t* src = g_ahi + (size_t)(n0 + row) * 128 + q * 32 + j * 4;
        CP_ASYNC16(dst, src);
    }
    CP_COMMIT();
    CP_WAIT0();
    __syncthreads();

    if (wid < 8) {
        // ================= TENSOR PATH: codes [0, CT) =================
        const int warp_m = wid >> 1;    // 0..3, m32
        const int warp_n = wid & 1;     // 0..1, n32

        uint32_t arow[2], arx[2];
        #pragma unroll
        for (int mt = 0; mt < 2; mt++) {
            int r = warp_m * 32 + mt * 16 + (lane & 15);
            arow[mt] = (uint32_t)r * 128;
            arx[mt]  = (uint32_t)((r & 7) << 4);
        }
        const uint32_t ahalf = (uint32_t)((lane >> 4) * 16);

        float insqr[4];
        #pragma unroll
        for (int i = 0; i < 4; i++) {
            int mt = i >> 1, hf = i & 1;
            insqr[i] = s_insq[warp_m * 32 + mt * 16 + hf * 8 + (lane >> 2)];
        }

        const u64* bbase = reinterpret_cast<const u64*>(g_bf) + warp_n * 128 + lane;
        float acc[2][4][4];

        for (int nt = 0; nt < CT / 64; nt++) {
            #pragma unroll
            for (int mt = 0; mt < 2; mt++)
                #pragma unroll
                for (int n8 = 0; n8 < 4; n8++)
                    #pragma unroll
                    for (int i = 0; i < 4; i++) acc[mt][n8][i] = 0.f;

            const u64* bp = bbase + (size_t)nt * 4096;
            u64 bc[4], bn[4];
            #pragma unroll
            for (int n8 = 0; n8 < 4; n8++) bc[n8] = __ldg(bp + n8 * 32);

            #pragma unroll
            for (int ks = 0; ks < 16; ks++) {
                if (ks < 15) {
                    const u64* np = bp + (ks + 1) * 256;
                    #pragma unroll
                    for (int n8 = 0; n8 < 4; n8++) bn[n8] = __ldg(np + n8 * 32);
                }
                const uint32_t qoff = (uint32_t)((ks >> 2) * 16384);
                const uint32_t kb = (uint32_t)((ks & 3) * 32);
                uint32_t a[2][4];
                #pragma unroll
                for (int mt = 0; mt < 2; mt++)
                    LDSM4(a[mt][0], a[mt][1], a[mt][2], a[mt][3],
                          sb + SM_AHI + qoff + arow[mt] + ((kb + ahalf) ^ arx[mt]));
                #pragma unroll
                for (int mt = 0; mt < 2; mt++)
                    #pragma unroll
                    for (int n8 = 0; n8 < 4; n8++)
                        MMA16816(acc[mt][n8], a[mt][0], a[mt][1], a[mt][2], a[mt][3],
                                 (uint32_t)bc[n8], (uint32_t)(bc[n8] >> 32));
                #pragma unroll
                for (int n8 = 0; n8 < 4; n8++) bc[n8] = bn[n8];
            }

            // fold: row minima -> atomicMin
            #pragma unroll
            for (int mt = 0; mt < 2; mt++) {
                #pragma unroll
                for (int hf = 0; hf < 2; hf++) {
                    const float iq = insqr[mt * 2 + hf];
                    float mn = __uint_as_float(0x7F800000u);
                    const int colbase = nt * 64 + warp_n * 32 + (lane & 3) * 2;
                    #pragma unroll
                    for (int n8 = 0; n8 < 4; n8++) {
                        #pragma unroll
                        for (int ci = 0; ci < 2; ci++) {
                            float tq = iq + s_cbsq[colbase + n8 * 8 + ci];
                            float dist = tq - 2.0f * acc[mt][n8][hf * 2 + ci];
                            mn = fminf(mn, dist);
                        }
                    }
                    float o1 = __shfl_xor_sync(0xFFFFFFFFu, mn, 1);
                    mn = fminf(mn, o1);
                    float o2 = __shfl_xor_sync(0xFFFFFFFFu, mn, 2);
                    mn = fminf(mn, o2);
                    if ((lane & 3) == 0) {
                        int row = warp_m * 32 + mt * 16 + hf * 8 + (lane >> 2);
                        atomicMin(&s_rowmin[row], __float_as_uint(mn));
                    }
                }
            }
            // append (rowmin-so-far + MARGIN >= final threshold => superset)
            #pragma unroll
            for (int mt = 0; mt < 2; mt++) {
                #pragma unroll
                for (int hf = 0; hf < 2; hf++) {
                    const int row = warp_m * 32 + mt * 16 + hf * 8 + (lane >> 2);
                    const float thr = __uint_as_float(s_rowmin[row]) + MARGIN;
                    const float iq = insqr[mt * 2 + hf];
                    const int colbase = nt * 64 + warp_n * 32 + (lane & 3) * 2;
                    #pragma unroll
                    for (int n8 = 0; n8 < 4; n8++) {
                        #pragma unroll
                        for (int ci = 0; ci < 2; ci++) {
                            float tq = iq + s_cbsq[colbase + n8 * 8 + ci];
                            float dist = tq - 2.0f * acc[mt][n8][hf * 2 + ci];
                            if (dist < thr) {
                                int pos = atomicAdd(&s_cnt[row], 1);
                                if (pos < MAXCAND)
                                    s_cand[row * MAXCAND + pos] =
                                        (uint32_t)(colbase + n8 * 8 + ci);
                            }
                        }
                    }
                }
            }
        }
    } else {
        // ================= FMA PATH: codes [CT, 1024), exact fp32 =============
        const int u  = t - 256;          // 0..255
        const int tx = u & 15;           // 16 code-groups (4 codes each)
        const int ty = u >> 4;           // 16 row-groups (8 rows each)

        u64 best8[8];
        #pragma unroll
        for (int i = 0; i < 8; i++) best8[i] = ~0ull;

        for (int kt = 0; kt < CF_T; kt++) {
            const int code0 = CT + kt * 64;
            u64 acc[4][4];   // [row-pair][code]
            #pragma unroll
            for (int p = 0; p < 4; p++)
                #pragma unroll
                for (int c = 0; c < 4; c++) acc[p][c] = 0ull;

            for (int d0 = 0; d0 < 256; d0 += 16) {
                // stage x (16 d x 128 rows) and cb (16 d x 64 codes)
                #pragma unroll
                for (int i = 0; i < 8; i++) {
                    int idx = u + i * 256;
                    int row = idx >> 4, dd = idx & 15;
                    s_sx[dd * 132 + row] = __ldg(&g_xt[(size_t)(n0 + row) * 256 + d0 + dd]);
                }
                #pragma unroll
                for (int i = 0; i < 4; i++) {
                    int idx = i * 256 + u;
                    int dd = idx & 15, cc = idx >> 4;
                    s_scb[dd * 68 + cc] = __ldg(&cb[(size_t)(code0 + cc) * 256 + d0 + dd]);
                }
                BAR1_256();
                #pragma unroll
                for (int dd = 0; dd < 16; dd++) {
                    u64 xp[4];
                    #pragma unroll
                    for (int p = 0; p < 4; p++)
                        xp[p] = *reinterpret_cast<const u64*>(&s_sx[dd * 132 + ty * 8 + p * 2]);
                    float4 cvv = *reinterpret_cast<const float4*>(&s_scb[dd * 68 + tx * 4]);
                    float cv[4] = {cvv.x, cvv.y, cvv.z, cvv.w};
                    #pragma unroll
                    for (int c = 0; c < 4; c++) {
                        u64 cpk = pack2(cv[c], cv[c]);
                        #pragma unroll
                        for (int p = 0; p < 4; p++) fma2(acc[p][c], xp[p], cpk);
                    }
                }
                BAR1_256();
            }

            // exact epilogue (same rounding as rescore): fold into best8
            #pragma unroll
            for (int c = 0; c < 4; c++) {
                int col = code0 + tx * 4 + c;
                float cbs = s_cbsq[col];
                #pragma unroll
                for (int p = 0; p < 4; p++) {
                    float a0, a1;
                    unpack2(acc[p][c], a0, a1);
                    int r0 = ty * 8 + p * 2;
                    float t0 = s_insq[r0] + cbs;
                    float d0v = t0 - 2.0f * a0;
                    u64 k0 = ((u64)__float_as_uint(d0v) << 32) | (unsigned)col;
                    if (k0 < best8[p * 2]) best8[p * 2] = k0;
                    float t1 = s_insq[r0 + 1] + cbs;
                    float d1v = t1 - 2.0f * a1;
                    u64 k1 = ((u64)__float_as_uint(d1v) << 32) | (unsigned)col;
                    if (k1 < best8[p * 2 + 1]) best8[p * 2 + 1] = k1;
                }
            }
        }

        // reduce across tx -> keyq slot 4
        #pragma unroll
        for (int i = 0; i < 8; i++) s_red[(ty * 8 + i) * 17 + tx] = best8[i];
        BAR1_256();
        if (u < 128) {
            u64 m = s_red[u * 17];
            #pragma unroll
            for (int j = 1; j < 16; j++) {
                u64 v = s_red[u * 17 + j];
                if (v < m) m = v;
            }
            s_keyq[4 * 128 + u] = m;
        }
    }
    __syncthreads();

    // ---- exact rescore of tensor candidates (4 threads per row) ----
    {
        const int row = t & 127;
        const int q4 = t >> 7;
        int cnt = s_cnt[row];
        const float iq = s_insq[row];
        const float* xr = &g_xt[(size_t)(n0 + row) * 256];
        u64 key = ~0ull;
        if (cnt > MAXCAND) {
            for (int col = q4; col < NCODE; col += 4) {
                const float* cr = cb + (size_t)col * 256;
                float dot = 0.f;
                #pragma unroll 8
                for (int d = 0; d < 256; d++) dot = fmaf(xr[d], cr[d], dot);
                float tq = iq + s_cbsq[col];
                float dist = tq - 2.0f * dot;
                u64 k = ((u64)__float_as_uint(dist) << 32) | (unsigned)col;
                if (k < key) key = k;
            }
        } else {
            for (int i = q4; i < cnt; i += 4) {
                int col = (int)s_cand[row * MAXCAND + i];
                const float* cr = cb + (size_t)col * 256;
                float dot = 0.f;
                #pragma unroll 8
                for (int d = 0; d < 256; d++) dot = fmaf(xr[d], cr[d], dot);
                float tq = iq + s_cbsq[col];
                float dist = tq - 2.0f * dot;
                u64 k = ((u64)__float_as_uint(dist) << 32) | (unsigned)col;
                if (k < key) key = k;
            }
        }
        s_keyq[q4 * 128 + row] = key;
    }
    __syncthreads();

    if (t < 128) {
        u64 best = s_keyq[t];
        #pragma unroll
        for (int q = 1; q < 5; q++) {
            u64 k2 = s_keyq[q * 128 + t];
            if (k2 < best) best = k2;
        }
        int kbest = (int)(unsigned)(best & 0xFFFFFFFFull);
        g_idx[n0 + t] = kbest;
        atomicAdd(&g_hist[kbest], 1);
    }
}

// ---------------- outputs ----------------
__global__ void k_ones(float* __restrict__ enc) {
    int n = blockIdx.x * 256 + threadIdx.x;
    enc[(size_t)n * NCODE + g_idx[n]] = 1.0f;
}

#define NGROUPS 4194303   // (XELEMS - 4) / 4
__global__ void k_xq(const float* __restrict__ x, const float* __restrict__ cb,
                     float* __restrict__ outb /* == out+1 */) {
    int j = blockIdx.x * blockDim.x + threadIdx.x;
    float lsum = 0.f;
    if (j < NGROUPS) {
        int i0 = 3 + 4 * j;
        float o[4];
        #pragma unroll
        for (int r = 0; r < 4; r++) {
            int i = i0 + r;
            int hw = i & 4095;
            int bd = i >> 12;
            int d = bd & 255, b = bd >> 8;
            int idx = g_idx[(b << 12) + hw];
            float xv = __ldg(x + i);
            float q = __ldg(cb + (size_t)idx * DIM + d);
            float diff = q - xv;
            lsum += diff * diff;
            o[r] = xv + diff;
        }
        *reinterpret_cast<float4*>(outb + i0) = make_float4(o[0], o[1], o[2], o[3]);
    } else if (j == NGROUPS) {
        const int spec[4] = {0, 1, 2, XELEMS - 1};
        #pragma unroll
        for (int r = 0; r < 4; r++) {
            int i = spec[r];
            int hw = i & 4095;
            int bd = i >> 12;
            int d = bd & 255, b = bd >> 8;
            int idx = g_idx[(b << 12) + hw];
            float xv = __ldg(x + i);
            float q = __ldg(cb + (size_t)idx * DIM + d);
            float diff = q - xv;
            lsum += diff * diff;
            outb[i] = xv + diff;
        }
    }
    #pragma unroll
    for (int off = 16; off; off >>= 1) lsum += __shfl_down_sync(0xFFFFFFFFu, lsum, off);
    __shared__ float warpsum[8];
    if ((threadIdx.x & 31) == 0) warpsum[threadIdx.x >> 5] = lsum;
    __syncthreads();
    if (threadIdx.x == 0) {
        float s = 0.f;
        #pragma unroll
        for (int w = 0; w < 8; w++) s += warpsum[w];
        atomicAdd(&g_losssum, (double)s);
    }
}

__global__ void k_fin(float* __restrict__ out_loss, float* __restrict__ out_perp) {
    __shared__ float sred[32];
    int t = threadIdx.x;
    float e_mean = (float)g_hist[t] * (1.0f / 65536.0f);
    float term = e_mean * logf(e_mean + 1e10f);
    #pragma unroll
    for (int off = 16; off; off >>= 1) term += __shfl_down_sync(0xFFFFFFFFu, term, off);
    if ((t & 31) == 0) sred[t >> 5] = term;
    __syncthreads();
    if (t < 32) {
        float v = sred[t];
        #pragma unroll
        for (int off = 16; off; off >>= 1) v += __shfl_down_sync(0xFFFFFFFFu, v, off);
        if (t == 0) {
            if (out_perp) *out_perp = expf(-v);
            if (out_loss) {
                float mse = (float)(g_losssum * (1.0 / 16777216.0));
                *out_loss = mse + 0.25f * mse;
            }
        }
    }
}

extern "C" void kernel_launch(void* const* d_in, const int* in_sizes, int n_in,
                              void* d_out, int out_size) {
    const float* x  = (const float*)d_in[0];
    const float* cb = (const float*)d_in[1];
    if (n_in >= 2 && in_sizes[0] == NCODE * DIM) {
        x  = (const float*)d_in[1];
        cb = (const float*)d_in[0];
    }

    float* out = (float*)d_out;
    float *o_loss = nullptr, *o_xq = nullptr, *o_perp = nullptr, *o_enc = nullptr;
    if (out_size == XELEMS) {
        o_xq = out;
    } else if (out_size == ENCELEMS) {
        o_enc = out;
    } else if (out_size == 2) {
        o_loss = out; o_perp = out + 1;
    } else {
        o_loss = out;
        o_xq   = out + 1;
        o_perp = out + 1 + XELEMS;
        o_enc  = out + 2 + XELEMS;
    }

    cudaFuncSetAttribute(k_dist, cudaFuncAttributeMaxDynamicSharedMemorySize, SM_TOTAL);

    // k_dist stays the 4th kernel launch (ncu capture lands on launch #4).
    k_zero<<<1, 1024>>>();
    k_prep<<<512, 256>>>(cb);
    k_split_x<<<NROWS / 32, 256>>>(x);
    k_dist<<<NROWS / 128, 512, SM_TOTAL>>>(cb);
    if (o_enc) {
        cudaMemsetAsync(o_enc, 0, (size_t)ENCELEMS * sizeof(float));
        k_ones<<<NROWS / 256, 256>>>(o_enc);
    }
    if (o_xq) k_xq<<<16384, 256>>>(x, cb, o_xq);
    k_fin<<<1, 1024>>>(o_loss, o_perp);
}

// round 11
// speedup vs baseline: 1.5082x; 1.5082x over previous
#include <cuda_runtime.h>
#include <cuda_fp16.h>
#include <cstdint>

#define BATCH   16
#define DIM     256
#define HWSZ    4096
#define NROWS   65536
#define NCODE   1024
#define XELEMS  16777216
#define ENCELEMS 67108864
#define MARGIN  4e-3f
#define MAXCAND 32

typedef unsigned long long u64;

// ---------------- scratch (device globals) ----------------
__device__ int      g_idx[NROWS];
__device__ int      g_hist[NCODE];
__device__ float    g_cbsq[NCODE];
__device__ float    g_insq[NROWS];
__device__ double   g_losssum;
__device__ float    g_xt[NROWS * 256];    // transposed x, fp32 [n][d]
__device__ uint32_t g_ahi[NROWS * 128];   // fp16x2 pairs, [n][d/2]
__device__ uint32_t g_bf[NCODE * 128];    // codebook fp16, MMA B-fragment order

// ---------------- PTX helpers (baseline sm_80 features only) ----------------
__device__ __forceinline__ uint32_t smem_u32(const void* p) {
    uint32_t a;
    asm("{ .reg .u64 t; cvta.to.shared.u64 t, %1; cvt.u32.u64 %0, t; }" : "=r"(a) : "l"(p));
    return a;
}
#define LDSM4(r0, r1, r2, r3, a) \
    asm volatile("ldmatrix.sync.aligned.m8n8.x4.shared.b16 {%0,%1,%2,%3}, [%4];" \
        : "=r"(r0), "=r"(r1), "=r"(r2), "=r"(r3) : "r"(a))
#define MMA16816(d, a0, a1, a2, a3, b0, b1) \
    asm volatile("mma.sync.aligned.m16n8k16.row.col.f32.f16.f16.f32 " \
        "{%0,%1,%2,%3}, {%4,%5,%6,%7}, {%8,%9}, {%0,%1,%2,%3};" \
        : "+f"((d)[0]), "+f"((d)[1]), "+f"((d)[2]), "+f"((d)[3]) \
        : "r"(a0), "r"(a1), "r"(a2), "r"(a3), "r"(b0), "r"(b1))
#define CP_ASYNC16(dst, src) \
    asm volatile("cp.async.cg.shared.global [%0], [%1], 16;" :: "r"(dst), "l"(src))
#define CP_COMMIT() asm volatile("cp.async.commit_group;" ::: "memory")
#define CP_WAIT0()  asm volatile("cp.async.wait_group 0;" ::: "memory")

// ---------------- SMEM layout for k_mma (dynamic) ----------------
#define SM_AHI    0          // 65536: A_hi resident, 4 tiles of [128][64 fp16]
#define SM_CBSQ   65536      // 4096
#define SM_INSQ   69632      // 512
#define SM_ROWMIN 70144      // 512 (float bits)
#define SM_CNT    70656      // 512
#define SM_CAND   71168      // 128*32*4 = 16384
#define SM_KEYQ   87552      // 512 u64 = 4096
#define SM_TOTAL  91648

// ---------------- small kernels ----------------
__global__ void k_zero() {
    int t = blockIdx.x * blockDim.x + threadIdx.x;
    if (t == 0) g_losssum = 0.0;
    if (t < NCODE) g_hist[t] = 0;
}

// codebook -> fp16 B-fragment order (128-wide n-tiles) + per-code sq norms
// m16n8k16 .row.col B fragment: lane holds B[k=2*(lane&3)+{0,1}][n=lane>>2] in
// word0, +8 in k for word1. u32 idx = (((nt*16+kstep)*16+n8g)*32+lane)*2+word.
__global__ void k_prep(const float* __restrict__ cb) {
    int i = blockIdx.x * 256 + threadIdx.x;      // over NCODE*128 u32 (d-pairs)
    int k = i >> 7;
    int d = (i & 127) * 2;
    float2 v = *reinterpret_cast<const float2*>(cb + (size_t)k * DIM + d);
    __half h0 = __float2half_rn(v.x);
    __half h1 = __float2half_rn(v.y);
    int nt = k >> 7, cc = k & 127;
    int n8g = cc >> 3;
    int lane = ((cc & 7) << 2) | ((d & 7) >> 1);
    int kstep = d >> 4;
    int word = (d >> 3) & 1;
    uint32_t idx = (uint32_t)((((nt * 16 + kstep) * 16 + n8g) * 32 + lane) * 2 + word);
    g_bf[idx] = ((uint32_t)__half_as_ushort(h1) << 16) | __half_as_ushort(h0);
    if (i < NCODE) {
        const float4* p = reinterpret_cast<const float4*>(cb + (size_t)i * DIM);
        float s = 0.f;
        #pragma unroll 8
        for (int dd = 0; dd < DIM / 4; dd++) {
            float4 q = p[dd];
            s += q.x * q.x; s += q.y * q.y; s += q.z * q.z; s += q.w * q.w;
        }
        g_cbsq[i] = s;
    }
}

// x NCHW -> a_hi [n][d] fp16x2 + g_xt fp32 + per-row |x|^2 (sequential-d)
__global__ void __launch_bounds__(256) k_split_x(const float* __restrict__ x) {
    __shared__ float s[256 * 33];
    const int t  = threadIdx.x;
    const int n0 = blockIdx.x * 32;
    const int b  = n0 >> 12;
    const int hw0 = n0 & 4095;
    const float* xb = x + (size_t)b * DIM * HWSZ + hw0;

    #pragma unroll
    for (int i = 0; i < 32; i++) {
        int lin = i * 256 + t;
        int d = lin >> 5, hw = lin & 31;
        s[d * 33 + hw] = xb[(size_t)d * HWSZ + hw];
    }
    __syncthreads();

    if (t < 32) {   // in_sq, sequential over d
        float acc = 0.f;
        #pragma unroll 8
        for (int d = 0; d < 256; d++) {
            float v = s[d * 33 + t];
            acc += v * v;
        }
        g_insq[n0 + t] = acc;
    }

    #pragma unroll
    for (int j = 0; j < 16; j++) {
        int lin = j * 256 + t;              // over 32*128 u32 outputs
        int nl = lin >> 7, c = lin & 127;
        float v0 = s[(2 * c) * 33 + nl];
        float v1 = s[(2 * c + 1) * 33 + nl];
        __half h0 = __float2half_rn(v0);
        __half h1 = __float2half_rn(v1);
        size_t o = (size_t)(n0 + nl) * 128 + c;
        g_ahi[o] = ((uint32_t)__half_as_ushort(h1) << 16) | __half_as_ushort(h0);
        float2* xt = reinterpret_cast<float2*>(&g_xt[(size_t)(n0 + nl) * 256 + 2 * c]);
        *xt = make_float2(v0, v1);
    }
}

// ---------------- mma.sync filter + exact-rescore argmin kernel ----------------
// Single-segment GEMM (K=256, hi*hi), hard error bound < 2e-3, MARGIN=4e-3.
// A SMEM-resident (LDSM); B streamed from L2 as pre-permuted fragments with a
// DEPTH-3 register prefetch pipeline (4-stage circular buffer) to hide the
// ~250-cycle L2 latency that bound rounds 7-9. No mainloop barriers.
__global__ void __launch_bounds__(512, 1) k_mma(const float* __restrict__ cb) {
    extern __shared__ __align__(1024) char smem[];
    const uint32_t sb = smem_u32(smem);
    const int t    = threadIdx.x;
    const int lane = t & 31;
    const int wid  = t >> 5;
    const int warp_m = wid >> 2;        // 0..3  (m32 each)
    const int warp_n = wid & 3;         // 0..3  (n32 each)
    const int n0   = blockIdx.x * 128;

    float* s_cbsq = reinterpret_cast<float*>(smem + SM_CBSQ);
    float* s_insq = reinterpret_cast<float*>(smem + SM_INSQ);
    uint32_t* s_rowmin = reinterpret_cast<uint32_t*>(smem + SM_ROWMIN);
    int* s_cnt = reinterpret_cast<int*>(smem + SM_CNT);
    uint32_t* s_cand = reinterpret_cast<uint32_t*>(smem + SM_CAND);
    u64* s_keyq = reinterpret_cast<u64*>(smem + SM_KEYQ);

    s_cbsq[t] = g_cbsq[t];
    s_cbsq[t + 512] = g_cbsq[t + 512];
    if (t < 128) {
        s_insq[t] = g_insq[n0 + t];
        s_rowmin[t] = 0x7F800000u;   // +inf
        s_cnt[t] = 0;
    }

    // ---- A_hi resident via cp.async (4096 16B segments; 8 per thread)
    #pragma unroll
    for (int i = 0; i < 8; i++) {
        int s = i * 512 + t;
        int q = s >> 10, rem = s & 1023;
        int row = rem >> 3, j = rem & 7;
        uint32_t dst = sb + SM_AHI + q * 16384 + row * 128 +
                       ((j * 16) ^ ((row & 7) << 4));
        const uint32_t* src = g_ahi + (size_t)(n0 + row) * 128 + q * 32 + j * 4;
        CP_ASYNC16(dst, src);
    }
    CP_COMMIT();

    // ---- per-lane ldmatrix address components (A only)
    uint32_t arow[2], arx[2];
    #pragma unroll
    for (int mt = 0; mt < 2; mt++) {
        int r = warp_m * 32 + mt * 16 + (lane & 15);
        arow[mt] = (uint32_t)r * 128;
        arx[mt]  = (uint32_t)((r & 7) << 4);
    }
    const uint32_t ahalf = (uint32_t)((lane >> 4) * 16);

    float insqr[4];
    float acc[2][4][4];   // [mt][n8][c]

    // B fragment stream: step s = nt*16+ks -> bbase + s*512 (u64), n8 at +n8*32
    const u64* bbase =
        reinterpret_cast<const u64*>(g_bf) + (warp_n * 4) * 32 + lane;

    // depth-3 prefetch: 4-stage circular register buffer
    u64 breg[4][4];
    #pragma unroll
    for (int s = 0; s < 3; s++)
        #pragma unroll
        for (int n8 = 0; n8 < 4; n8++)
            breg[s][n8] = __ldg(bbase + (size_t)s * 512 + n8 * 32);

    CP_WAIT0();
    __syncthreads();      // A + cbsq/insq/rowmin/cnt visible

    #pragma unroll
    for (int i = 0; i < 4; i++) {
        int mt = i >> 1, hf = i & 1;
        insqr[i] = s_insq[warp_m * 32 + mt * 16 + hf * 8 + (lane >> 2)];
    }

    for (int nt = 0; nt < 8; nt++) {
        #pragma unroll
        for (int mt = 0; mt < 2; mt++)
            #pragma unroll
            for (int n8 = 0; n8 < 4; n8++)
                #pragma unroll
                for (int i = 0; i < 4; i++) acc[mt][n8][i] = 0.f;

        #pragma unroll
        for (int ks = 0; ks < 16; ks++) {
            const int step = nt * 16 + ks;      // nt*16 ≡ 0 mod 4 -> masks compile-time
            // prefetch step+3 into stage (ks+3)&3
            if (step + 3 < 128) {
                const u64* np = bbase + (size_t)(step + 3) * 512;
                #pragma unroll
                for (int n8 = 0; n8 < 4; n8++)
                    breg[(ks + 3) & 3][n8] = __ldg(np + n8 * 32);
            }
            const uint32_t qoff = (uint32_t)((ks >> 2) * 16384);
            const uint32_t kb = (uint32_t)((ks & 3) * 32);
            uint32_t a[2][4];
            #pragma unroll
            for (int mt = 0; mt < 2; mt++)
                LDSM4(a[mt][0], a[mt][1], a[mt][2], a[mt][3],
                      sb + SM_AHI + qoff + arow[mt] + ((kb + ahalf) ^ arx[mt]));
            #pragma unroll
            for (int mt = 0; mt < 2; mt++)
                #pragma unroll
                for (int n8 = 0; n8 < 4; n8++)
                    MMA16816(acc[mt][n8], a[mt][0], a[mt][1], a[mt][2], a[mt][3],
                             (uint32_t)breg[ks & 3][n8],
                             (uint32_t)(breg[ks & 3][n8] >> 32));
        }

        // fold: warp-group row minima -> atomicMin (no barrier needed)
        #pragma unroll
        for (int mt = 0; mt < 2; mt++) {
            #pragma unroll
            for (int hf = 0; hf < 2; hf++) {
                const float iq = insqr[mt * 2 + hf];
                float mn = __uint_as_float(0x7F800000u);
                const int colbase = nt * 128 + warp_n * 32 + (lane & 3) * 2;
                #pragma unroll
                for (int n8 = 0; n8 < 4; n8++) {
                    #pragma unroll
                    for (int ci = 0; ci < 2; ci++) {
                        float tq = iq + s_cbsq[colbase + n8 * 8 + ci];
                        float dist = tq - 2.0f * acc[mt][n8][hf * 2 + ci];
                        mn = fminf(mn, dist);
                    }
                }
                float o1 = __shfl_xor_sync(0xFFFFFFFFu, mn, 1);
                mn = fminf(mn, o1);
                float o2 = __shfl_xor_sync(0xFFFFFFFFu, mn, 2);
                mn = fminf(mn, o2);
                if ((lane & 3) == 0) {
                    int row = warp_m * 32 + mt * 16 + hf * 8 + (lane >> 2);
                    atomicMin(&s_rowmin[row], __float_as_uint(mn));
                }
            }
        }
        // append: rowmin-so-far + MARGIN >= final threshold => superset;
        // overflow handled by exact fallback in the rescore phase.
        #pragma unroll
        for (int mt = 0; mt < 2; mt++) {
            #pragma unroll
            for (int hf = 0; hf < 2; hf++) {
                const int row = warp_m * 32 + mt * 16 + hf * 8 + (lane >> 2);
                const float thr = __uint_as_float(s_rowmin[row]) + MARGIN;
                const float iq = insqr[mt * 2 + hf];
                const int colbase = nt * 128 + warp_n * 32 + (lane & 3) * 2;
                #pragma unroll
                for (int n8 = 0; n8 < 4; n8++) {
                    #pragma unroll
                    for (int ci = 0; ci < 2; ci++) {
                        float tq = iq + s_cbsq[colbase + n8 * 8 + ci];
                        float dist = tq - 2.0f * acc[mt][n8][hf * 2 + ci];
                        if (dist < thr) {
                            int pos = atomicAdd(&s_cnt[row], 1);
                            if (pos < MAXCAND)
                                s_cand[row * MAXCAND + pos] =
                                    (uint32_t)(colbase + n8 * 8 + ci);
                        }
                    }
                }
            }
        }
    }
    __syncthreads();

    // ---- exact rescore (bit-identical to the round-2 fp32 arithmetic) ----
    {
        const int row = t & 127;
        const int q4 = t >> 7;            // 0..3: split candidates 4 ways
        int cnt = s_cnt[row];
        const float iq = s_insq[row];
        const float* xr = &g_xt[(size_t)(n0 + row) * 256];
        u64 key = ~0ull;
        if (cnt > MAXCAND) {
            // overflow fallback: exact scan of ALL codes (rare/never)
            for (int col = q4; col < NCODE; col += 4) {
                const float* cr = cb + (size_t)col * 256;
                float dot = 0.f;
                #pragma unroll 8
                for (int d = 0; d < 256; d++) dot = fmaf(xr[d], cr[d], dot);
                float tq = iq + s_cbsq[col];
                float dist = tq - 2.0f * dot;
                u64 k = ((u64)__float_as_uint(dist) << 32) | (unsigned)col;
                if (k < key) key = k;
            }
        } else {
            for (int i = q4; i < cnt; i += 4) {
                int col = (int)s_cand[row * MAXCAND + i];
                const float* cr = cb + (size_t)col * 256;
                float dot = 0.f;
                #pragma unroll 8
                for (int d = 0; d < 256; d++) dot = fmaf(xr[d], cr[d], dot);
                float tq = iq + s_cbsq[col];
                float dist = tq - 2.0f * dot;
                u64 k = ((u64)__float_as_uint(dist) << 32) | (unsigned)col;
                if (k < key) key = k;
            }
        }
        s_keyq[q4 * 128 + row] = key;
        __syncthreads();
        if (t < 128) {
            u64 best = s_keyq[row];
            #pragma unroll
            for (int q = 1; q < 4; q++) {
                u64 k2 = s_keyq[q * 128 + row];
                if (k2 < best) best = k2;
            }
            int kbest = (int)(unsigned)(best & 0xFFFFFFFFull);
            g_idx[n0 + row] = kbest;
            atomicAdd(&g_hist[kbest], 1);
        }
    }
}

// ---------------- outputs ----------------
__global__ void k_ones(float* __restrict__ enc) {
    int n = blockIdx.x * 256 + threadIdx.x;
    enc[(size_t)n * NCODE + g_idx[n]] = 1.0f;
}

#define NGROUPS 4194303   // (XELEMS - 4) / 4
__global__ void k_xq(const float* __restrict__ x, const float* __restrict__ cb,
                     float* __restrict__ outb /* == out+1 */) {
    int j = blockIdx.x * blockDim.x + threadIdx.x;
    float lsum = 0.f;
    if (j < NGROUPS) {
        int i0 = 3 + 4 * j;
        float o[4];
        #pragma unroll
        for (int r = 0; r < 4; r++) {
            int i = i0 + r;
            int hw = i & 4095;
            int bd = i >> 12;
            int d = bd & 255, b = bd >> 8;
            int idx = g_idx[(b << 12) + hw];
            float xv = __ldg(x + i);
            float q = __ldg(cb + (size_t)idx * DIM + d);
            float diff = q - xv;
            lsum += diff * diff;
            o[r] = xv + diff;
        }
        *reinterpret_cast<float4*>(outb + i0) = make_float4(o[0], o[1], o[2], o[3]);
    } else if (j == NGROUPS) {
        const int spec[4] = {0, 1, 2, XELEMS - 1};
        #pragma unroll
        for (int r = 0; r < 4; r++) {
            int i = spec[r];
            int hw = i & 4095;
            int bd = i >> 12;
            int d = bd & 255, b = bd >> 8;
            int idx = g_idx[(b << 12) + hw];
            float xv = __ldg(x + i);
            float q = __ldg(cb + (size_t)idx * DIM + d);
            float diff = q - xv;
            lsum += diff * diff;
            outb[i] = xv + diff;
        }
    }
    #pragma unroll
    for (int off = 16; off; off >>= 1) lsum += __shfl_down_sync(0xFFFFFFFFu, lsum, off);
    __shared__ float warpsum[8];
    if ((threadIdx.x & 31) == 0) warpsum[threadIdx.x >> 5] = lsum;
    __syncthreads();
    if (threadIdx.x == 0) {
        float s = 0.f;
        #pragma unroll
        for (int w = 0; w < 8; w++) s += warpsum[w];
        atomicAdd(&g_losssum, (double)s);
    }
}

__global__ void k_fin(float* __restrict__ out_loss, float* __restrict__ out_perp) {
    __shared__ float sred[32];
    int t = threadIdx.x;
    float e_mean = (float)g_hist[t] * (1.0f / 65536.0f);
    float term = e_mean * logf(e_mean + 1e10f);
    #pragma unroll
    for (int off = 16; off; off >>= 1) term += __shfl_down_sync(0xFFFFFFFFu, term, off);
    if ((t & 31) == 0) sred[t >> 5] = term;
    __syncthreads();
    if (t < 32) {
        float v = sred[t];
        #pragma unroll
        for (int off = 16; off; off >>= 1) v += __shfl_down_sync(0xFFFFFFFFu, v, off);
        if (t == 0) {
            if (out_perp) *out_perp = expf(-v);
            if (out_loss) {
                float mse = (float)(g_losssum * (1.0 / 16777216.0));
                *out_loss = mse + 0.25f * mse;
            }
        }
    }
}

extern "C" void kernel_launch(void* const* d_in, const int* in_sizes, int n_in,
                              void* d_out, int out_size) {
    const float* x  = (const float*)d_in[0];
    const float* cb = (const float*)d_in[1];
    if (n_in >= 2 && in_sizes[0] == NCODE * DIM) {
        x  = (const float*)d_in[1];
        cb = (const float*)d_in[0];
    }

    float* out = (float*)d_out;
    float *o_loss = nullptr, *o_xq = nullptr, *o_perp = nullptr, *o_enc = nullptr;
    if (out_size == XELEMS) {
        o_xq = out;
    } else if (out_size == ENCELEMS) {
        o_enc = out;
    } else if (out_size == 2) {
        o_loss = out; o_perp = out + 1;
    } else {
        o_loss = out;
        o_xq   = out + 1;
        o_perp = out + 1 + XELEMS;
        o_enc  = out + 2 + XELEMS;
    }

    cudaFuncSetAttribute(k_mma, cudaFuncAttributeMaxDynamicSharedMemorySize, SM_TOTAL);

    // k_mma stays the 4th kernel launch (ncu capture lands on launch #4).
    k_zero<<<1, 1024>>>();
    k_prep<<<512, 256>>>(cb);
    k_split_x<<<NROWS / 32, 256>>>(x);
    k_mma<<<NROWS / 128, 512, SM_TOTAL>>>(cb);
    if (o_enc) {
        cudaMemsetAsync(o_enc, 0, (size_t)ENCELEMS * sizeof(float));
        k_ones<<<NROWS / 256, 256>>>(o_enc);
    }
    if (o_xq) k_xq<<<16384, 256>>>(x, cb, o_xq);
    k_fin<<<1, 1024>>>(o_loss, o_perp);
}

// round 12
// speedup vs baseline: 3.0247x; 2.0056x over previous
#include <cuda_runtime.h>
#include <cuda_fp16.h>
#include <cstdint>

#define BATCH   16
#define DIM     256
#define HWSZ    4096
#define NROWS   65536
#define NCODE   1024
#define XELEMS  16777216
#define ENCELEMS 67108864
#define MARGIN  4e-3f
#define MAXCAND 32

typedef unsigned long long u64;

// ---------------- scratch (device globals) ----------------
__device__ int      g_idx[NROWS];
__device__ int      g_hist[NCODE];
__device__ float    g_cbsq[NCODE];
__device__ float    g_insq[NROWS];
__device__ double   g_losssum;
__device__ float    g_xt[NROWS * 256];        // transposed x, fp32 [n][d]
__device__ uint32_t g_ahi[NROWS * 128];       // fp16x2 pairs, [n][d/2]
__device__ uint32_t g_bf[NCODE * 128];        // codebook fp16, MMA B-fragment order
__device__ int      g_cnt[NROWS];             // candidate counts
__device__ uint32_t g_cand[NROWS * MAXCAND];  // candidate code ids

// ---------------- PTX helpers (baseline sm_80 features only) ----------------
__device__ __forceinline__ uint32_t smem_u32(const void* p) {
    uint32_t a;
    asm("{ .reg .u64 t; cvta.to.shared.u64 t, %1; cvt.u32.u64 %0, t; }" : "=r"(a) : "l"(p));
    return a;
}
#define LDSM4(r0, r1, r2, r3, a) \
    asm volatile("ldmatrix.sync.aligned.m8n8.x4.shared.b16 {%0,%1,%2,%3}, [%4];" \
        : "=r"(r0), "=r"(r1), "=r"(r2), "=r"(r3) : "r"(a))
#define MMA16816(d, a0, a1, a2, a3, b0, b1) \
    asm volatile("mma.sync.aligned.m16n8k16.row.col.f32.f16.f16.f32 " \
        "{%0,%1,%2,%3}, {%4,%5,%6,%7}, {%8,%9}, {%0,%1,%2,%3};" \
        : "+f"((d)[0]), "+f"((d)[1]), "+f"((d)[2]), "+f"((d)[3]) \
        : "r"(a0), "r"(a1), "r"(a2), "r"(a3), "r"(b0), "r"(b1))
#define CP_ASYNC16(dst, src) \
    asm volatile("cp.async.cg.shared.global [%0], [%1], 16;" :: "r"(dst), "l"(src))
#define CP_COMMIT() asm volatile("cp.async.commit_group;" ::: "memory")
#define CP_WAIT0()  asm volatile("cp.async.wait_group 0;" ::: "memory")

// ---------------- SMEM layout for k_mma (dynamic) ----------------
#define SM_AHI    0          // 65536: A_hi resident, 4 tiles of [128][64 fp16]
#define SM_CBSQ   65536      // 4096
#define SM_INSQ   69632      // 512
#define SM_ROWMIN 70144      // 512 (float bits)
#define SM_CNT    70656      // 512
#define SM_CAND   71168      // 128*32*4 = 16384
#define SM_TOTAL  87552

// ---------------- small kernels ----------------
__global__ void k_zero() {
    int t = blockIdx.x * blockDim.x + threadIdx.x;
    if (t == 0) g_losssum = 0.0;
    if (t < NCODE) g_hist[t] = 0;
}

// codebook -> fp16 B-fragment order (128-wide n-tiles) + per-code sq norms
__global__ void k_prep(const float* __restrict__ cb) {
    int i = blockIdx.x * 256 + threadIdx.x;      // over NCODE*128 u32 (d-pairs)
    int k = i >> 7;
    int d = (i & 127) * 2;
    float2 v = *reinterpret_cast<const float2*>(cb + (size_t)k * DIM + d);
    __half h0 = __float2half_rn(v.x);
    __half h1 = __float2half_rn(v.y);
    int nt = k >> 7, cc = k & 127;
    int n8g = cc >> 3;
    int lane = ((cc & 7) << 2) | ((d & 7) >> 1);
    int kstep = d >> 4;
    int word = (d >> 3) & 1;
    uint32_t idx = (uint32_t)((((nt * 16 + kstep) * 16 + n8g) * 32 + lane) * 2 + word);
    g_bf[idx] = ((uint32_t)__half_as_ushort(h1) << 16) | __half_as_ushort(h0);
    if (i < NCODE) {
        const float4* p = reinterpret_cast<const float4*>(cb + (size_t)i * DIM);
        float s = 0.f;
        #pragma unroll 8
        for (int dd = 0; dd < DIM / 4; dd++) {
            float4 q = p[dd];
            s += q.x * q.x; s += q.y * q.y; s += q.z * q.z; s += q.w * q.w;
        }
        g_cbsq[i] = s;
    }
}

// x NCHW -> a_hi [n][d] fp16x2 + g_xt fp32 + per-row |x|^2 (sequential-d)
__global__ void __launch_bounds__(256) k_split_x(const float* __restrict__ x) {
    __shared__ float s[256 * 33];
    const int t  = threadIdx.x;
    const int n0 = blockIdx.x * 32;
    const int b  = n0 >> 12;
    const int hw0 = n0 & 4095;
    const float* xb = x + (size_t)b * DIM * HWSZ + hw0;

    #pragma unroll
    for (int i = 0; i < 32; i++) {
        int lin = i * 256 + t;
        int d = lin >> 5, hw = lin & 31;
        s[d * 33 + hw] = xb[(size_t)d * HWSZ + hw];
    }
    __syncthreads();

    if (t < 32) {   // in_sq, sequential over d
        float acc = 0.f;
        #pragma unroll 8
        for (int d = 0; d < 256; d++) {
            float v = s[d * 33 + t];
            acc += v * v;
        }
        g_insq[n0 + t] = acc;
    }

    #pragma unroll
    for (int j = 0; j < 16; j++) {
        int lin = j * 256 + t;              // over 32*128 u32 outputs
        int nl = lin >> 7, c = lin & 127;
        float v0 = s[(2 * c) * 33 + nl];
        float v1 = s[(2 * c + 1) * 33 + nl];
        __half h0 = __float2half_rn(v0);
        __half h1 = __float2half_rn(v1);
        size_t o = (size_t)(n0 + nl) * 128 + c;
        g_ahi[o] = ((uint32_t)__half_as_ushort(h1) << 16) | __half_as_ushort(h0);
        float2* xt = reinterpret_cast<float2*>(&g_xt[(size_t)(n0 + nl) * 256 + 2 * c]);
        *xt = make_float2(v0, v1);
    }
}

// ---------------- mma.sync filter kernel (candidates -> global) ----------------
// Single-segment GEMM (K=256, hi*hi), hard error bound < 2e-3, MARGIN=4e-3.
// A SMEM-resident (LDSM); B streamed as pre-permuted fragments via LDG.64.
// Epilogue computes each dist ONCE, guards the append behind a per-thread min
// test. Candidates + counts are dumped to global for k_rescore.
__global__ void __launch_bounds__(512, 1) k_mma() {
    extern __shared__ __align__(1024) char smem[];
    const uint32_t sb = smem_u32(smem);
    const int t    = threadIdx.x;
    const int lane = t & 31;
    const int wid  = t >> 5;
    const int warp_m = wid >> 2;        // 0..3  (m32 each)
    const int warp_n = wid & 3;         // 0..3  (n32 each)
    const int n0   = blockIdx.x * 128;

    float* s_cbsq = reinterpret_cast<float*>(smem + SM_CBSQ);
    float* s_insq = reinterpret_cast<float*>(smem + SM_INSQ);
    uint32_t* s_rowmin = reinterpret_cast<uint32_t*>(smem + SM_ROWMIN);
    int* s_cnt = reinterpret_cast<int*>(smem + SM_CNT);
    uint32_t* s_cand = reinterpret_cast<uint32_t*>(smem + SM_CAND);

    s_cbsq[t] = g_cbsq[t];
    s_cbsq[t + 512] = g_cbsq[t + 512];
    if (t < 128) {
        s_insq[t] = g_insq[n0 + t];
        s_rowmin[t] = 0x7F800000u;   // +inf
        s_cnt[t] = 0;
    }

    // ---- A_hi resident via cp.async (4096 16B segments; 8 per thread)
    #pragma unroll
    for (int i = 0; i < 8; i++) {
        int s = i * 512 + t;
        int q = s >> 10, rem = s & 1023;
        int row = rem >> 3, j = rem & 7;
        uint32_t dst = sb + SM_AHI + q * 16384 + row * 128 +
                       ((j * 16) ^ ((row & 7) << 4));
        const uint32_t* src = g_ahi + (size_t)(n0 + row) * 128 + q * 32 + j * 4;
        CP_ASYNC16(dst, src);
    }
    CP_COMMIT();

    // ---- per-lane ldmatrix address components (A only)
    uint32_t arow[2], arx[2];
    #pragma unroll
    for (int mt = 0; mt < 2; mt++) {
        int r = warp_m * 32 + mt * 16 + (lane & 15);
        arow[mt] = (uint32_t)r * 128;
        arx[mt]  = (uint32_t)((r & 7) << 4);
    }
    const uint32_t ahalf = (uint32_t)((lane >> 4) * 16);

    float insqr[4];
    float acc[2][4][4];   // [mt][n8][c]

    const u64* bbase =
        reinterpret_cast<const u64*>(g_bf) + (warp_n * 4) * 32 + lane;

    CP_WAIT0();
    __syncthreads();      // A + cbsq/insq/rowmin/cnt visible

    #pragma unroll
    for (int i = 0; i < 4; i++) {
        int mt = i >> 1, hf = i & 1;
        insqr[i] = s_insq[warp_m * 32 + mt * 16 + hf * 8 + (lane >> 2)];
    }

    for (int nt = 0; nt < 8; nt++) {
        #pragma unroll
        for (int mt = 0; mt < 2; mt++)
            #pragma unroll
            for (int n8 = 0; n8 < 4; n8++)
                #pragma unroll
                for (int i = 0; i < 4; i++) acc[mt][n8][i] = 0.f;

        const u64* bp = bbase + (size_t)nt * 16 * 16 * 32;
        u64 bc[4], bn[4];
        #pragma unroll
        for (int n8 = 0; n8 < 4; n8++) bc[n8] = __ldg(bp + n8 * 32);

        #pragma unroll
        for (int ks = 0; ks < 16; ks++) {
            if (ks < 15) {
                const u64* np = bp + (ks + 1) * 512;
                #pragma unroll
                for (int n8 = 0; n8 < 4; n8++) bn[n8] = __ldg(np + n8 * 32);
            }
            const uint32_t qoff = (uint32_t)((ks >> 2) * 16384);
            const uint32_t kb = (uint32_t)((ks & 3) * 32);
            uint32_t a[2][4];
            #pragma unroll
            for (int mt = 0; mt < 2; mt++)
                LDSM4(a[mt][0], a[mt][1], a[mt][2], a[mt][3],
                      sb + SM_AHI + qoff + arow[mt] + ((kb + ahalf) ^ arx[mt]));
            #pragma unroll
            for (int mt = 0; mt < 2; mt++)
                #pragma unroll
                for (int n8 = 0; n8 < 4; n8++)
                    MMA16816(acc[mt][n8], a[mt][0], a[mt][1], a[mt][2], a[mt][3],
                             (uint32_t)bc[n8], (uint32_t)(bc[n8] >> 32));
            #pragma unroll
            for (int n8 = 0; n8 < 4; n8++) bc[n8] = bn[n8];
        }

        // ---- epilogue: compute all 32 dists ONCE, fold, guarded append ----
        const int colbase = nt * 128 + warp_n * 32 + (lane & 3) * 2;
        float dl[32];     // [(mt*2+hf)*8 + n8*2 + ci]
        float mnl[4];
        #pragma unroll
        for (int mt = 0; mt < 2; mt++) {
            #pragma unroll
            for (int hf = 0; hf < 2; hf++) {
                const float iq = insqr[mt * 2 + hf];
                float mn = __uint_as_float(0x7F800000u);
                #pragma unroll
                for (int n8 = 0; n8 < 4; n8++) {
                    #pragma unroll
                    for (int ci = 0; ci < 2; ci++) {
                        float tq = iq + s_cbsq[colbase + n8 * 8 + ci];
                        float dist = tq - 2.0f * acc[mt][n8][hf * 2 + ci];
                        dl[(mt * 2 + hf) * 8 + n8 * 2 + ci] = dist;
                        mn = fminf(mn, dist);
                    }
                }
                mnl[mt * 2 + hf] = mn;
                float o1 = __shfl_xor_sync(0xFFFFFFFFu, mn, 1);
                mn = fminf(mn, o1);
                float o2 = __shfl_xor_sync(0xFFFFFFFFu, mn, 2);
                mn = fminf(mn, o2);
                if ((lane & 3) == 0) {
                    int row = warp_m * 32 + mt * 16 + hf * 8 + (lane >> 2);
                    if (mn < __uint_as_float(s_rowmin[row]))
                        atomicMin(&s_rowmin[row], __float_as_uint(mn));
                }
            }
        }
        // append (superset: rowmin only decreases); most threads skip entirely
        #pragma unroll
        for (int i = 0; i < 4; i++) {
            const int mt = i >> 1, hf = i & 1;
            const int row = warp_m * 32 + mt * 16 + hf * 8 + (lane >> 2);
            const float thr = __uint_as_float(s_rowmin[row]) + MARGIN;
            if (mnl[i] < thr) {
                #pragma unroll
                for (int j = 0; j < 8; j++) {
                    if (dl[i * 8 + j] < thr) {
                        int pos = atomicAdd(&s_cnt[row], 1);
                        if (pos < MAXCAND)
                            s_cand[row * MAXCAND + pos] =
                                (uint32_t)(colbase + (j >> 1) * 8 + (j & 1));
                    }
                }
            }
        }
    }
    __syncthreads();

    // ---- dump candidates + counts to global (coalesced) ----
    if (t < 128) g_cnt[n0 + t] = s_cnt[t];
    #pragma unroll
    for (int i = 0; i < (128 * MAXCAND) / 512; i++)
        g_cand[(size_t)n0 * MAXCAND + i * 512 + t] = s_cand[i * 512 + t];
}

// ---------------- exact rescore kernel (one warp per row) ----------------
// Stages xt row + up to 8 candidate cb rows into shared COALESCED, then 8
// lanes run the bit-identical sequential-d fp32 fmaf chain each on its own
// candidate. Overflow (cnt > MAXCAND) falls back to scanning all 1024 codes.
__global__ void __launch_bounds__(256) k_rescore(const float* __restrict__ cb) {
    extern __shared__ float rs[];
    float* xt_sh = rs;                       // [w][260]
    float* cb_sh = rs + 8 * 260;             // [w*8+ci][260]
    int*   cols  = (int*)(rs + 8 * 260 + 64 * 260);  // [w*8+ci]

    const int w = threadIdx.x >> 5;
    const int lane = threadIdx.x & 31;
    const int n = blockIdx.x * 8 + w;

    int cnt = g_cnt[n];
    const bool full = cnt > MAXCAND;
    const int m = full ? NCODE : cnt;

    // stage xt row (coalesced float4)
    #pragma unroll
    for (int j = 0; j < 2; j++) {
        int f4 = j * 32 + lane;
        float4 v = *reinterpret_cast<const float4*>(&g_xt[(size_t)n * 256 + f4 * 4]);
        float* dst = &xt_sh[w * 260 + f4 * 4];
        dst[0] = v.x; dst[1] = v.y; dst[2] = v.z; dst[3] = v.w;
    }
    const float iq = g_insq[n];
    u64 best = ~0ull;

    for (int b0 = 0; b0 < m; b0 += 8) {
        int nb = m - b0; if (nb > 8) nb = 8;
        if (lane < 8) {
            int col = 0;
            if (lane < nb)
                col = full ? (b0 + lane)
                           : (int)g_cand[(size_t)n * MAXCAND + b0 + lane];
            cols[w * 8 + lane] = col;
        }
        __syncwarp();
        // stage nb cb rows, coalesced float4 (nb*64 float4 over 32 lanes)
        for (int j = lane; j < nb * 64; j += 32) {
            int ci = j >> 6, f4 = j & 63;
            float4 v = *reinterpret_cast<const float4*>(
                &cb[(size_t)cols[w * 8 + ci] * 256 + f4 * 4]);
            float* dst = &cb_sh[(w * 8 + ci) * 260 + f4 * 4];
            dst[0] = v.x; dst[1] = v.y; dst[2] = v.z; dst[3] = v.w;
        }
        __syncwarp();
        if (lane < nb) {
            int col = cols[w * 8 + lane];
            const float* xr = &xt_sh[w * 260];
            const float* cr = &cb_sh[(w * 8 + lane) * 260];
            float dot = 0.f;
            #pragma unroll 8
            for (int d = 0; d < 256; d++) dot = fmaf(xr[d], cr[d], dot);
            float tq = iq + g_cbsq[col];
            float dist = tq - 2.0f * dot;
            u64 k = ((u64)__float_as_uint(dist) << 32) | (unsigned)col;
            if (k < best) best = k;
        }
        __syncwarp();
    }

    // min over lanes 0..7
    #pragma unroll
    for (int off = 4; off; off >>= 1) {
        u64 o = __shfl_xor_sync(0xFFFFFFFFu, best, off);
        if (o < best) best = o;
    }
    if (lane == 0) {
        int kbest = (int)(unsigned)(best & 0xFFFFFFFFull);
        g_idx[n] = kbest;
        atomicAdd(&g_hist[kbest], 1);
    }
}
#define RS_SMEM ((8 * 260 + 64 * 260) * 4 + 64 * 4)

// ---------------- outputs ----------------
__global__ void k_ones(float* __restrict__ enc) {
    int n = blockIdx.x * 256 + threadIdx.x;
    enc[(size_t)n * NCODE + g_idx[n]] = 1.0f;
}

// coalesced xq: block = (b, 32 hw) x 256 d; codebook rows staged in shared
__global__ void __launch_bounds__(256) k_xq2(const float* __restrict__ x,
                                             const float* __restrict__ cb,
                                             float* __restrict__ outb) {
    __shared__ float cbs[32 * 261];
    __shared__ int idxs[32];
    __shared__ float warpsum[8];
    const int t = threadIdx.x;
    const int b = blockIdx.x >> 7;
    const int hw0 = (blockIdx.x & 127) << 5;
    const int n0 = (b << 12) + hw0;
    if (t < 32) idxs[t] = g_idx[n0 + t];
    __syncthreads();
    #pragma unroll
    for (int j = 0; j < 8; j++) {
        int lin = j * 256 + t;               // 2048 = 32 rows x 64 float4
        int row = lin >> 6, f4 = lin & 63;
        float4 v = *reinterpret_cast<const float4*>(
            &cb[(size_t)idxs[row] * 256 + f4 * 4]);
        float* dst = &cbs[row * 261 + f4 * 4];
        dst[0] = v.x; dst[1] = v.y; dst[2] = v.z; dst[3] = v.w;
    }
    __syncthreads();
    const int hw = t & 31, dg = t >> 5;
    float lsum = 0.f;
    #pragma unroll 4
    for (int dj = 0; dj < 32; dj++) {
        int d = dg * 32 + dj;
        size_t gi = (((size_t)b * 256 + d) << 12) + hw0 + hw;
        float xv = __ldg(x + gi);
        float q = cbs[hw * 261 + d];
        float diff = q - xv;      // fl(xq - xp)
        lsum += diff * diff;
        outb[gi] = xv + diff;     // fl(xp + fl(xq - xp))
    }
    #pragma unroll
    for (int off = 16; off; off >>= 1) lsum += __shfl_down_sync(0xFFFFFFFFu, lsum, off);
    if ((t & 31) == 0) warpsum[t >> 5] = lsum;
    __syncthreads();
    if (t == 0) {
        float s = 0.f;
        #pragma unroll
        for (int ww = 0; ww < 8; ww++) s += warpsum[ww];
        atomicAdd(&g_losssum, (double)s);
    }
}

__global__ void k_fin(float* __restrict__ out_loss, float* __restrict__ out_perp) {
    __shared__ float sred[32];
    int t = threadIdx.x;
    float e_mean = (float)g_hist[t] * (1.0f / 65536.0f);
    float term = e_mean * logf(e_mean + 1e10f);
    #pragma unroll
    for (int off = 16; off; off >>= 1) term += __shfl_down_sync(0xFFFFFFFFu, term, off);
    if ((t & 31) == 0) sred[t >> 5] = term;
    __syncthreads();
    if (t < 32) {
        float v = sred[t];
        #pragma unroll
        for (int off = 16; off; off >>= 1) v += __shfl_down_sync(0xFFFFFFFFu, v, off);
        if (t == 0) {
            if (out_perp) *out_perp = expf(-v);
            if (out_loss) {
                float mse = (float)(g_losssum * (1.0 / 16777216.0));
                *out_loss = mse + 0.25f * mse;
            }
        }
    }
}

extern "C" void kernel_launch(void* const* d_in, const int* in_sizes, int n_in,
                              void* d_out, int out_size) {
    const float* x  = (const float*)d_in[0];
    const float* cb = (const float*)d_in[1];
    if (n_in >= 2 && in_sizes[0] == NCODE * DIM) {
        x  = (const float*)d_in[1];
        cb = (const float*)d_in[0];
    }

    float* out = (float*)d_out;
    float *o_loss = nullptr, *o_xq = nullptr, *o_perp = nullptr, *o_enc = nullptr;
    if (out_size == XELEMS) {
        o_xq = out;
    } else if (out_size == ENCELEMS) {
        o_enc = out;
    } else if (out_size == 2) {
        o_loss = out; o_perp = out + 1;
    } else {
        o_loss = out;
        o_xq   = out + 1;
        o_perp = out + 1 + XELEMS;
        o_enc  = out + 2 + XELEMS;
    }

    cudaFuncSetAttribute(k_mma, cudaFuncAttributeMaxDynamicSharedMemorySize, SM_TOTAL);
    cudaFuncSetAttribute(k_rescore, cudaFuncAttributeMaxDynamicSharedMemorySize, RS_SMEM);

    // k_mma stays the 4th kernel launch (ncu capture lands on launch #4) —
    // now WITHOUT the rescore, so the profile isolates the mainloop+epilogue.
    k_zero<<<1, 1024>>>();
    k_prep<<<512, 256>>>(cb);
    k_split_x<<<NROWS / 32, 256>>>(x);
    k_mma<<<NROWS / 128, 512, SM_TOTAL>>>();
    k_rescore<<<NROWS / 8, 256, RS_SMEM>>>(cb);
    if (o_enc) {
        cudaMemsetAsync(o_enc, 0, (size_t)ENCELEMS * sizeof(float));
        k_ones<<<NROWS / 256, 256>>>(o_enc);
    }
    if (o_xq) k_xq2<<<2048, 256>>>(x, cb, o_xq);
    k_fin<<<1, 1024>>>(o_loss, o_perp);
}

// round 13
// speedup vs baseline: 3.0533x; 1.0095x over previous
#include <cuda_runtime.h>
#include <cuda_fp16.h>
#include <cstdint>

#define BATCH   16
#define DIM     256
#define HWSZ    4096
#define NROWS   65536
#define NCODE   1024
#define XELEMS  16777216
#define ENCELEMS 67108864
#define MARGIN  4e-3f
#define MAXCAND 32

typedef unsigned long long u64;

// ---------------- scratch (device globals) ----------------
__device__ int      g_idx[NROWS];
__device__ int      g_hist[NCODE];
__device__ float    g_cbsq[NCODE];
__device__ float    g_insq[NROWS];
__device__ double   g_losssum;
__device__ float    g_xt[NROWS * 256];        // transposed x, fp32 [n][d]
__device__ uint32_t g_ahi[NROWS * 128];       // fp16x2 pairs, [n][d/2]
__device__ uint32_t g_bf[NCODE * 128];        // codebook fp16, MMA B-fragment order
__device__ int      g_cnt[NROWS];             // candidate counts
__device__ uint32_t g_cand[NROWS * MAXCAND];  // candidate code ids

// ---------------- PTX helpers (baseline sm_80 features only) ----------------
__device__ __forceinline__ uint32_t smem_u32(const void* p) {
    uint32_t a;
    asm("{ .reg .u64 t; cvta.to.shared.u64 t, %1; cvt.u32.u64 %0, t; }" : "=r"(a) : "l"(p));
    return a;
}
#define LDSM4(r0, r1, r2, r3, a) \
    asm volatile("ldmatrix.sync.aligned.m8n8.x4.shared.b16 {%0,%1,%2,%3}, [%4];" \
        : "=r"(r0), "=r"(r1), "=r"(r2), "=r"(r3) : "r"(a))
#define MMA16816(d, a0, a1, a2, a3, b0, b1) \
    asm volatile("mma.sync.aligned.m16n8k16.row.col.f32.f16.f16.f32 " \
        "{%0,%1,%2,%3}, {%4,%5,%6,%7}, {%8,%9}, {%0,%1,%2,%3};" \
        : "+f"((d)[0]), "+f"((d)[1]), "+f"((d)[2]), "+f"((d)[3]) \
        : "r"(a0), "r"(a1), "r"(a2), "r"(a3), "r"(b0), "r"(b1))
#define CP_ASYNC16(dst, src) \
    asm volatile("cp.async.cg.shared.global [%0], [%1], 16;" :: "r"(dst), "l"(src))
#define CP_COMMIT() asm volatile("cp.async.commit_group;" ::: "memory")
#define CP_WAIT0()  asm volatile("cp.async.wait_group 0;" ::: "memory")

// ---------------- SMEM layout for k_mma (dynamic) ----------------
#define SM_AHI    0          // 65536: A_hi resident, 4 tiles of [128][64 fp16]
#define SM_CBSQ   65536      // 4096
#define SM_INSQ   69632      // 512
#define SM_ROWMIN 70144      // 512 (float bits)
#define SM_CNT    70656      // 512
#define SM_CAND   71168      // 128*32*4 = 16384
#define SM_TOTAL  87552

// ---------------- prep: zero accum + codebook fragments + norms ----------------
__global__ void k_prep(const float* __restrict__ cb) {
    int i = blockIdx.x * 256 + threadIdx.x;      // over NCODE*128 u32 (d-pairs)
    if (i == 0) g_losssum = 0.0;
    int k = i >> 7;
    int d = (i & 127) * 2;
    float2 v = *reinterpret_cast<const float2*>(cb + (size_t)k * DIM + d);
    __half h0 = __float2half_rn(v.x);
    __half h1 = __float2half_rn(v.y);
    int nt = k >> 7, cc = k & 127;
    int n8g = cc >> 3;
    int lane = ((cc & 7) << 2) | ((d & 7) >> 1);
    int kstep = d >> 4;
    int word = (d >> 3) & 1;
    uint32_t idx = (uint32_t)((((nt * 16 + kstep) * 16 + n8g) * 32 + lane) * 2 + word);
    g_bf[idx] = ((uint32_t)__half_as_ushort(h1) << 16) | __half_as_ushort(h0);
    if (i < NCODE) {
        g_hist[i] = 0;
        const float4* p = reinterpret_cast<const float4*>(cb + (size_t)i * DIM);
        float s = 0.f;
        #pragma unroll 8
        for (int dd = 0; dd < DIM / 4; dd++) {
            float4 q = p[dd];
            s += q.x * q.x; s += q.y * q.y; s += q.z * q.z; s += q.w * q.w;
        }
        g_cbsq[i] = s;
    }
}

// x NCHW -> a_hi [n][d] fp16x2 + g_xt fp32 + per-row |x|^2 (sequential-d)
__global__ void __launch_bounds__(256) k_split_x(const float* __restrict__ x) {
    __shared__ float s[256 * 33];
    const int t  = threadIdx.x;
    const int n0 = blockIdx.x * 32;
    const int b  = n0 >> 12;
    const int hw0 = n0 & 4095;
    const float* xb = x + (size_t)b * DIM * HWSZ + hw0;

    #pragma unroll
    for (int i = 0; i < 32; i++) {
        int lin = i * 256 + t;
        int d = lin >> 5, hw = lin & 31;
        s[d * 33 + hw] = xb[(size_t)d * HWSZ + hw];
    }
    __syncthreads();

    if (t < 32) {   // in_sq, sequential over d
        float acc = 0.f;
        #pragma unroll 8
        for (int d = 0; d < 256; d++) {
            float v = s[d * 33 + t];
            acc += v * v;
        }
        g_insq[n0 + t] = acc;
    }

    #pragma unroll
    for (int j = 0; j < 16; j++) {
        int lin = j * 256 + t;              // over 32*128 u32 outputs
        int nl = lin >> 7, c = lin & 127;
        float v0 = s[(2 * c) * 33 + nl];
        float v1 = s[(2 * c + 1) * 33 + nl];
        __half h0 = __float2half_rn(v0);
        __half h1 = __float2half_rn(v1);
        size_t o = (size_t)(n0 + nl) * 128 + c;
        g_ahi[o] = ((uint32_t)__half_as_ushort(h1) << 16) | __half_as_ushort(h0);
        float2* xt = reinterpret_cast<float2*>(&g_xt[(size_t)(n0 + nl) * 256 + 2 * c]);
        *xt = make_float2(v0, v1);
    }
}

// ---------------- mma.sync filter kernel (candidates -> global) ----------------
__global__ void __launch_bounds__(512, 1) k_mma() {
    extern __shared__ __align__(1024) char smem[];
    const uint32_t sb = smem_u32(smem);
    const int t    = threadIdx.x;
    const int lane = t & 31;
    const int wid  = t >> 5;
    const int warp_m = wid >> 2;        // 0..3  (m32 each)
    const int warp_n = wid & 3;         // 0..3  (n32 each)
    const int n0   = blockIdx.x * 128;

    float* s_cbsq = reinterpret_cast<float*>(smem + SM_CBSQ);
    float* s_insq = reinterpret_cast<float*>(smem + SM_INSQ);
    uint32_t* s_rowmin = reinterpret_cast<uint32_t*>(smem + SM_ROWMIN);
    int* s_cnt = reinterpret_cast<int*>(smem + SM_CNT);
    uint32_t* s_cand = reinterpret_cast<uint32_t*>(smem + SM_CAND);

    s_cbsq[t] = g_cbsq[t];
    s_cbsq[t + 512] = g_cbsq[t + 512];
    if (t < 128) {
        s_insq[t] = g_insq[n0 + t];
        s_rowmin[t] = 0x7F800000u;   // +inf
        s_cnt[t] = 0;
    }

    // ---- A_hi resident via cp.async (4096 16B segments; 8 per thread)
    #pragma unroll
    for (int i = 0; i < 8; i++) {
        int s = i * 512 + t;
        int q = s >> 10, rem = s & 1023;
        int row = rem >> 3, j = rem & 7;
        uint32_t dst = sb + SM_AHI + q * 16384 + row * 128 +
                       ((j * 16) ^ ((row & 7) << 4));
        const uint32_t* src = g_ahi + (size_t)(n0 + row) * 128 + q * 32 + j * 4;
        CP_ASYNC16(dst, src);
    }
    CP_COMMIT();

    // ---- per-lane ldmatrix address components (A only)
    uint32_t arow[2], arx[2];
    #pragma unroll
    for (int mt = 0; mt < 2; mt++) {
        int r = warp_m * 32 + mt * 16 + (lane & 15);
        arow[mt] = (uint32_t)r * 128;
        arx[mt]  = (uint32_t)((r & 7) << 4);
    }
    const uint32_t ahalf = (uint32_t)((lane >> 4) * 16);

    float insqr[4];
    float acc[2][4][4];   // [mt][n8][c]

    const u64* bbase =
        reinterpret_cast<const u64*>(g_bf) + (warp_n * 4) * 32 + lane;

    CP_WAIT0();
    __syncthreads();      // A + cbsq/insq/rowmin/cnt visible

    #pragma unroll
    for (int i = 0; i < 4; i++) {
        int mt = i >> 1, hf = i & 1;
        insqr[i] = s_insq[warp_m * 32 + mt * 16 + hf * 8 + (lane >> 2)];
    }

    for (int nt = 0; nt < 8; nt++) {
        #pragma unroll
        for (int mt = 0; mt < 2; mt++)
            #pragma unroll
            for (int n8 = 0; n8 < 4; n8++)
                #pragma unroll
                for (int i = 0; i < 4; i++) acc[mt][n8][i] = 0.f;

        const u64* bp = bbase + (size_t)nt * 16 * 16 * 32;
        u64 bc[4], bn[4];
        #pragma unroll
        for (int n8 = 0; n8 < 4; n8++) bc[n8] = __ldg(bp + n8 * 32);

        #pragma unroll
        for (int ks = 0; ks < 16; ks++) {
            if (ks < 15) {
                const u64* np = bp + (ks + 1) * 512;
                #pragma unroll
                for (int n8 = 0; n8 < 4; n8++) bn[n8] = __ldg(np + n8 * 32);
            }
            const uint32_t qoff = (uint32_t)((ks >> 2) * 16384);
            const uint32_t kb = (uint32_t)((ks & 3) * 32);
            uint32_t a[2][4];
            #pragma unroll
            for (int mt = 0; mt < 2; mt++)
                LDSM4(a[mt][0], a[mt][1], a[mt][2], a[mt][3],
                      sb + SM_AHI + qoff + arow[mt] + ((kb + ahalf) ^ arx[mt]));
            #pragma unroll
            for (int mt = 0; mt < 2; mt++)
                #pragma unroll
                for (int n8 = 0; n8 < 4; n8++)
                    MMA16816(acc[mt][n8], a[mt][0], a[mt][1], a[mt][2], a[mt][3],
                             (uint32_t)bc[n8], (uint32_t)(bc[n8] >> 32));
            #pragma unroll
            for (int n8 = 0; n8 < 4; n8++) bc[n8] = bn[n8];
        }

        // ---- epilogue: compute all 32 dists ONCE, fold, guarded append ----
        const int colbase = nt * 128 + warp_n * 32 + (lane & 3) * 2;
        float dl[32];     // [(mt*2+hf)*8 + n8*2 + ci]
        float mnl[4];
        #pragma unroll
        for (int mt = 0; mt < 2; mt++) {
            #pragma unroll
            for (int hf = 0; hf < 2; hf++) {
                const float iq = insqr[mt * 2 + hf];
                float mn = __uint_as_float(0x7F800000u);
                #pragma unroll
                for (int n8 = 0; n8 < 4; n8++) {
                    #pragma unroll
                    for (int ci = 0; ci < 2; ci++) {
                        float tq = iq + s_cbsq[colbase + n8 * 8 + ci];
                        float dist = tq - 2.0f * acc[mt][n8][hf * 2 + ci];
                        dl[(mt * 2 + hf) * 8 + n8 * 2 + ci] = dist;
                        mn = fminf(mn, dist);
                    }
                }
                mnl[mt * 2 + hf] = mn;
                float o1 = __shfl_xor_sync(0xFFFFFFFFu, mn, 1);
                mn = fminf(mn, o1);
                float o2 = __shfl_xor_sync(0xFFFFFFFFu, mn, 2);
                mn = fminf(mn, o2);
                if ((lane & 3) == 0) {
                    int row = warp_m * 32 + mt * 16 + hf * 8 + (lane >> 2);
                    if (mn < __uint_as_float(s_rowmin[row]))
                        atomicMin(&s_rowmin[row], __float_as_uint(mn));
                }
            }
        }
        #pragma unroll
        for (int i = 0; i < 4; i++) {
            const int mt = i >> 1, hf = i & 1;
            const int row = warp_m * 32 + mt * 16 + hf * 8 + (lane >> 2);
            const float thr = __uint_as_float(s_rowmin[row]) + MARGIN;
            if (mnl[i] < thr) {
                #pragma unroll
                for (int j = 0; j < 8; j++) {
                    if (dl[i * 8 + j] < thr) {
                        int pos = atomicAdd(&s_cnt[row], 1);
                        if (pos < MAXCAND)
                            s_cand[row * MAXCAND + pos] =
                                (uint32_t)(colbase + (j >> 1) * 8 + (j & 1));
                    }
                }
            }
        }
    }
    __syncthreads();

    // ---- dump candidates + counts to global (coalesced) ----
    if (t < 128) g_cnt[n0 + t] = s_cnt[t];
    #pragma unroll
    for (int i = 0; i < (128 * MAXCAND) / 512; i++)
        g_cand[(size_t)n0 * MAXCAND + i * 512 + t] = s_cand[i * 512 + t];
}

// ---------------- exact rescore kernel (one warp per row) ----------------
// cnt==1 fast path: the single surviving candidate IS the argmin (the true
// argmin is provably in the candidate set). Otherwise stage xt + candidate cb
// rows coalesced into shared, run bit-identical sequential-d fp32 chains.
__global__ void __launch_bounds__(256) k_rescore(const float* __restrict__ cb) {
    extern __shared__ float rs[];
    float* xt_sh = rs;                       // [w][260]
    float* cb_sh = rs + 8 * 260;             // [w*8+ci][260]
    int*   cols  = (int*)(rs + 8 * 260 + 64 * 260);  // [w*8+ci]

    const int w = threadIdx.x >> 5;
    const int lane = threadIdx.x & 31;
    const int n = blockIdx.x * 8 + w;

    int cnt = g_cnt[n];
    if (cnt == 1) {
        if (lane == 0) {
            int kbest = (int)g_cand[(size_t)n * MAXCAND];
            g_idx[n] = kbest;
            atomicAdd(&g_hist[kbest], 1);
        }
        return;   // warp-local exit; kernel has no block-wide syncs
    }
    const bool full = cnt > MAXCAND;
    const int m = full ? NCODE : cnt;

    // stage xt row (coalesced float4)
    #pragma unroll
    for (int j = 0; j < 2; j++) {
        int f4 = j * 32 + lane;
        float4 v = *reinterpret_cast<const float4*>(&g_xt[(size_t)n * 256 + f4 * 4]);
        float* dst = &xt_sh[w * 260 + f4 * 4];
        dst[0] = v.x; dst[1] = v.y; dst[2] = v.z; dst[3] = v.w;
    }
    const float iq = g_insq[n];
    u64 best = ~0ull;

    for (int b0 = 0; b0 < m; b0 += 8) {
        int nb = m - b0; if (nb > 8) nb = 8;
        if (lane < 8) {
            int col = 0;
            if (lane < nb)
                col = full ? (b0 + lane)
                           : (int)g_cand[(size_t)n * MAXCAND + b0 + lane];
            cols[w * 8 + lane] = col;
        }
        __syncwarp();
        for (int j = lane; j < nb * 64; j += 32) {
            int ci = j >> 6, f4 = j & 63;
            float4 v = *reinterpret_cast<const float4*>(
                &cb[(size_t)cols[w * 8 + ci] * 256 + f4 * 4]);
            float* dst = &cb_sh[(w * 8 + ci) * 260 + f4 * 4];
            dst[0] = v.x; dst[1] = v.y; dst[2] = v.z; dst[3] = v.w;
        }
        __syncwarp();
        if (lane < nb) {
            int col = cols[w * 8 + lane];
            const float* xr = &xt_sh[w * 260];
            const float* cr = &cb_sh[(w * 8 + lane) * 260];
            float dot = 0.f;
            #pragma unroll 8
            for (int d = 0; d < 256; d++) dot = fmaf(xr[d], cr[d], dot);
            float tq = iq + g_cbsq[col];
            float dist = tq - 2.0f * dot;
            u64 k = ((u64)__float_as_uint(dist) << 32) | (unsigned)col;
            if (k < best) best = k;
        }
        __syncwarp();
    }

    // min over lanes 0..7
    #pragma unroll
    for (int off = 4; off; off >>= 1) {
        u64 o = __shfl_xor_sync(0xFFFFFFFFu, best, off);
        if (o < best) best = o;
    }
    if (lane == 0) {
        int kbest = (int)(unsigned)(best & 0xFFFFFFFFull);
        g_idx[n] = kbest;
        atomicAdd(&g_hist[kbest], 1);
    }
}
#define RS_SMEM ((8 * 260 + 64 * 260) * 4 + 64 * 4)

// ---------------- outputs ----------------
__global__ void k_ones(float* __restrict__ enc) {
    int n = blockIdx.x * 256 + threadIdx.x;
    enc[(size_t)n * NCODE + g_idx[n]] = 1.0f;
}

// coalesced xq: block = (b, 32 hw) x 256 d; codebook rows staged in shared.
// x read as float4 along hw (aligned); stores scalar (outb = out+1, 4B-aligned).
__global__ void __launch_bounds__(256) k_xq2(const float* __restrict__ x,
                                             const float* __restrict__ cb,
                                             float* __restrict__ outb) {
    __shared__ float cbs[32 * 261];
    __shared__ int idxs[32];
    __shared__ float warpsum[8];
    const int t = threadIdx.x;
    const int b = blockIdx.x >> 7;
    const int hw0 = (blockIdx.x & 127) << 5;
    const int n0 = (b << 12) + hw0;
    if (t < 32) idxs[t] = g_idx[n0 + t];
    __syncthreads();
    #pragma unroll
    for (int j = 0; j < 8; j++) {
        int lin = j * 256 + t;               // 2048 = 32 rows x 64 float4
        int row = lin >> 6, f4 = lin & 63;
        float4 v = *reinterpret_cast<const float4*>(
            &cb[(size_t)idxs[row] * 256 + f4 * 4]);
        float* dst = &cbs[row * 261 + f4 * 4];
        dst[0] = v.x; dst[1] = v.y; dst[2] = v.z; dst[3] = v.w;
    }
    __syncthreads();
    float lsum = 0.f;
    #pragma unroll
    for (int i2 = 0; i2 < 8; i2++) {
        int f4 = i2 * 256 + t;               // 2048 float4 tiles
        int d = f4 >> 3, hw4 = (f4 & 7) * 4;
        size_t gi = (((size_t)b * 256 + d) << 12) + hw0 + hw4;
        float4 xv = *reinterpret_cast<const float4*>(x + gi);
        float q0 = cbs[(hw4 + 0) * 261 + d];
        float q1 = cbs[(hw4 + 1) * 261 + d];
        float q2 = cbs[(hw4 + 2) * 261 + d];
        float q3 = cbs[(hw4 + 3) * 261 + d];
        float d0 = q0 - xv.x, d1 = q1 - xv.y, d2 = q2 - xv.z, d3 = q3 - xv.w;
        lsum += d0 * d0; lsum += d1 * d1; lsum += d2 * d2; lsum += d3 * d3;
        outb[gi]     = xv.x + d0;
        outb[gi + 1] = xv.y + d1;
        outb[gi + 2] = xv.z + d2;
        outb[gi + 3] = xv.w + d3;
    }
    #pragma unroll
    for (int off = 16; off; off >>= 1) lsum += __shfl_down_sync(0xFFFFFFFFu, lsum, off);
    if ((t & 31) == 0) warpsum[t >> 5] = lsum;
    __syncthreads();
    if (t == 0) {
        float s = 0.f;
        #pragma unroll
        for (int ww = 0; ww < 8; ww++) s += warpsum[ww];
        atomicAdd(&g_losssum, (double)s);
    }
}

__global__ void k_fin(float* __restrict__ out_loss, float* __restrict__ out_perp) {
    __shared__ float sred[32];
    int t = threadIdx.x;
    float e_mean = (float)g_hist[t] * (1.0f / 65536.0f);
    float term = e_mean * logf(e_mean + 1e10f);
    #pragma unroll
    for (int off = 16; off; off >>= 1) term += __shfl_down_sync(0xFFFFFFFFu, term, off);
    if ((t & 31) == 0) sred[t >> 5] = term;
    __syncthreads();
    if (t < 32) {
        float v = sred[t];
        #pragma unroll
        for (int off = 16; off; off >>= 1) v += __shfl_down_sync(0xFFFFFFFFu, v, off);
        if (t == 0) {
            if (out_perp) *out_perp = expf(-v);
            if (out_loss) {
                float mse = (float)(g_losssum * (1.0 / 16777216.0));
                *out_loss = mse + 0.25f * mse;
            }
        }
    }
}

extern "C" void kernel_launch(void* const* d_in, const int* in_sizes, int n_in,
                              void* d_out, int out_size) {
    const float* x  = (const float*)d_in[0];
    const float* cb = (const float*)d_in[1];
    if (n_in >= 2 && in_sizes[0] == NCODE * DIM) {
        x  = (const float*)d_in[1];
        cb = (const float*)d_in[0];
    }

    float* out = (float*)d_out;
    float *o_loss = nullptr, *o_xq = nullptr, *o_perp = nullptr, *o_enc = nullptr;
    if (out_size == XELEMS) {
        o_xq = out;
    } else if (out_size == ENCELEMS) {
        o_enc = out;
    } else if (out_size == 2) {
        o_loss = out; o_perp = out + 1;
    } else {
        o_loss = out;
        o_xq   = out + 1;
        o_perp = out + 1 + XELEMS;
        o_enc  = out + 2 + XELEMS;
    }

    cudaFuncSetAttribute(k_mma, cudaFuncAttributeMaxDynamicSharedMemorySize, SM_TOTAL);
    cudaFuncSetAttribute(k_rescore, cudaFuncAttributeMaxDynamicSharedMemorySize, RS_SMEM);

    // k_rescore is now the 4th kernel launch (ncu capture lands on launch #4)
    // so next round's profile attributes the non-GEMM time sink.
    k_prep<<<512, 256>>>(cb);
    k_split_x<<<NROWS / 32, 256>>>(x);
    k_mma<<<NROWS / 128, 512, SM_TOTAL>>>();
    k_rescore<<<NROWS / 8, 256, RS_SMEM>>>(cb);
    if (o_enc) {
        cudaMemsetAsync(o_enc, 0, (size_t)ENCELEMS * sizeof(float));
        k_ones<<<NROWS / 256, 256>>>(o_enc);
    }
    if (o_xq) k_xq2<<<2048, 256>>>(x, cb, o_xq);
    k_fin<<<1, 1024>>>(o_loss, o_perp);
}

// round 14
// speedup vs baseline: 3.4483x; 1.1294x over previous
#include <cuda_runtime.h>
#include <cuda_fp16.h>
#include <cstdint>

#define BATCH   16
#define DIM     256
#define HWSZ    4096
#define NROWS   65536
#define NCODE   1024
#define XELEMS  16777216
#define ENCELEMS 67108864
#define MARGIN  4e-3f
#define MAXCAND 32

typedef unsigned long long u64;

// ---------------- scratch (device globals) ----------------
__device__ int      g_idx[NROWS];
__device__ int      g_hist[NCODE];
__device__ float    g_cbsq[NCODE];
__device__ float    g_insq[NROWS];
__device__ double   g_losssum;
__device__ float    g_xt[NROWS * 256];        // transposed x, fp32 [n][d]
__device__ uint32_t g_ahi[NROWS * 128];       // fp16x2 pairs, [n][d/2]
__device__ uint32_t g_bf[NCODE * 128];        // codebook fp16, MMA B-fragment order
__device__ int      g_cnt[NROWS];             // candidate counts
__device__ uint32_t g_cand[NROWS * MAXCAND];  // candidate code ids

// ---------------- PTX helpers (baseline sm_80 features only) ----------------
__device__ __forceinline__ uint32_t smem_u32(const void* p) {
    uint32_t a;
    asm("{ .reg .u64 t; cvta.to.shared.u64 t, %1; cvt.u32.u64 %0, t; }" : "=r"(a) : "l"(p));
    return a;
}
#define LDSM4(r0, r1, r2, r3, a) \
    asm volatile("ldmatrix.sync.aligned.m8n8.x4.shared.b16 {%0,%1,%2,%3}, [%4];" \
        : "=r"(r0), "=r"(r1), "=r"(r2), "=r"(r3) : "r"(a))
#define MMA16816(d, a0, a1, a2, a3, b0, b1) \
    asm volatile("mma.sync.aligned.m16n8k16.row.col.f32.f16.f16.f32 " \
        "{%0,%1,%2,%3}, {%4,%5,%6,%7}, {%8,%9}, {%0,%1,%2,%3};" \
        : "+f"((d)[0]), "+f"((d)[1]), "+f"((d)[2]), "+f"((d)[3]) \
        : "r"(a0), "r"(a1), "r"(a2), "r"(a3), "r"(b0), "r"(b1))
#define CP_ASYNC16(dst, src) \
    asm volatile("cp.async.cg.shared.global [%0], [%1], 16;" :: "r"(dst), "l"(src))
#define CP_COMMIT() asm volatile("cp.async.commit_group;" ::: "memory")
#define CP_WAIT0()  asm volatile("cp.async.wait_group 0;" ::: "memory")

// ---------------- SMEM layout for k_mma (dynamic) ----------------
#define SM_AHI    0          // 65536: A_hi resident, 4 tiles of [128][64 fp16]
#define SM_CBSQ   65536      // 4096
#define SM_INSQ   69632      // 512
#define SM_ROWMIN 70144      // 512 (float bits)
#define SM_CNT    70656      // 512
#define SM_CAND   71168      // 128*32*4 = 16384
#define SM_TOTAL  87552

// ---------------- prep: zero accum + codebook fragments + norms ----------------
__global__ void k_prep(const float* __restrict__ cb) {
    int i = blockIdx.x * 256 + threadIdx.x;      // over NCODE*128 u32 (d-pairs)
    if (i == 0) g_losssum = 0.0;
    int k = i >> 7;
    int d = (i & 127) * 2;
    float2 v = *reinterpret_cast<const float2*>(cb + (size_t)k * DIM + d);
    __half h0 = __float2half_rn(v.x);
    __half h1 = __float2half_rn(v.y);
    int nt = k >> 7, cc = k & 127;
    int n8g = cc >> 3;
    int lane = ((cc & 7) << 2) | ((d & 7) >> 1);
    int kstep = d >> 4;
    int word = (d >> 3) & 1;
    uint32_t idx = (uint32_t)((((nt * 16 + kstep) * 16 + n8g) * 32 + lane) * 2 + word);
    g_bf[idx] = ((uint32_t)__half_as_ushort(h1) << 16) | __half_as_ushort(h0);
    if (i < NCODE) {
        g_hist[i] = 0;
        const float4* p = reinterpret_cast<const float4*>(cb + (size_t)i * DIM);
        float s = 0.f;
        #pragma unroll 8
        for (int dd = 0; dd < DIM / 4; dd++) {
            float4 q = p[dd];
            s += q.x * q.x; s += q.y * q.y; s += q.z * q.z; s += q.w * q.w;
        }
        g_cbsq[i] = s;
    }
}

// x NCHW -> a_hi [n][d] fp16x2 + g_xt fp32 + per-row |x|^2 (sequential-d)
__global__ void __launch_bounds__(256) k_split_x(const float* __restrict__ x) {
    __shared__ float s[256 * 33];
    const int t  = threadIdx.x;
    const int n0 = blockIdx.x * 32;
    const int b  = n0 >> 12;
    const int hw0 = n0 & 4095;
    const float* xb = x + (size_t)b * DIM * HWSZ + hw0;

    #pragma unroll
    for (int i = 0; i < 32; i++) {
        int lin = i * 256 + t;
        int d = lin >> 5, hw = lin & 31;
        s[d * 33 + hw] = xb[(size_t)d * HWSZ + hw];
    }
    __syncthreads();

    if (t < 32) {   // in_sq, sequential over d
        float acc = 0.f;
        #pragma unroll 8
        for (int d = 0; d < 256; d++) {
            float v = s[d * 33 + t];
            acc += v * v;
        }
        g_insq[n0 + t] = acc;
    }

    #pragma unroll
    for (int j = 0; j < 16; j++) {
        int lin = j * 256 + t;              // over 32*128 u32 outputs
        int nl = lin >> 7, c = lin & 127;
        float v0 = s[(2 * c) * 33 + nl];
        float v1 = s[(2 * c + 1) * 33 + nl];
        __half h0 = __float2half_rn(v0);
        __half h1 = __float2half_rn(v1);
        size_t o = (size_t)(n0 + nl) * 128 + c;
        g_ahi[o] = ((uint32_t)__half_as_ushort(h1) << 16) | __half_as_ushort(h0);
        float2* xt = reinterpret_cast<float2*>(&g_xt[(size_t)(n0 + nl) * 256 + 2 * c]);
        *xt = make_float2(v0, v1);
    }
}

// ---------------- mma.sync filter kernel (candidates -> global) ----------------
__global__ void __launch_bounds__(512, 1) k_mma() {
    extern __shared__ __align__(1024) char smem[];
    const uint32_t sb = smem_u32(smem);
    const int t    = threadIdx.x;
    const int lane = t & 31;
    const int wid  = t >> 5;
    const int warp_m = wid >> 2;        // 0..3  (m32 each)
    const int warp_n = wid & 3;         // 0..3  (n32 each)
    const int n0   = blockIdx.x * 128;

    float* s_cbsq = reinterpret_cast<float*>(smem + SM_CBSQ);
    float* s_insq = reinterpret_cast<float*>(smem + SM_INSQ);
    uint32_t* s_rowmin = reinterpret_cast<uint32_t*>(smem + SM_ROWMIN);
    int* s_cnt = reinterpret_cast<int*>(smem + SM_CNT);
    uint32_t* s_cand = reinterpret_cast<uint32_t*>(smem + SM_CAND);

    s_cbsq[t] = g_cbsq[t];
    s_cbsq[t + 512] = g_cbsq[t + 512];
    if (t < 128) {
        s_insq[t] = g_insq[n0 + t];
        s_rowmin[t] = 0x7F800000u;   // +inf
        s_cnt[t] = 0;
    }

    // ---- A_hi resident via cp.async (4096 16B segments; 8 per thread)
    #pragma unroll
    for (int i = 0; i < 8; i++) {
        int s = i * 512 + t;
        int q = s >> 10, rem = s & 1023;
        int row = rem >> 3, j = rem & 7;
        uint32_t dst = sb + SM_AHI + q * 16384 + row * 128 +
                       ((j * 16) ^ ((row & 7) << 4));
        const uint32_t* src = g_ahi + (size_t)(n0 + row) * 128 + q * 32 + j * 4;
        CP_ASYNC16(dst, src);
    }
    CP_COMMIT();

    // ---- per-lane ldmatrix address components (A only)
    uint32_t arow[2], arx[2];
    #pragma unroll
    for (int mt = 0; mt < 2; mt++) {
        int r = warp_m * 32 + mt * 16 + (lane & 15);
        arow[mt] = (uint32_t)r * 128;
        arx[mt]  = (uint32_t)((r & 7) << 4);
    }
    const uint32_t ahalf = (uint32_t)((lane >> 4) * 16);

    float insqr[4];
    float acc[2][4][4];   // [mt][n8][c]

    const u64* bbase =
        reinterpret_cast<const u64*>(g_bf) + (warp_n * 4) * 32 + lane;

    CP_WAIT0();
    __syncthreads();      // A + cbsq/insq/rowmin/cnt visible

    #pragma unroll
    for (int i = 0; i < 4; i++) {
        int mt = i >> 1, hf = i & 1;
        insqr[i] = s_insq[warp_m * 32 + mt * 16 + hf * 8 + (lane >> 2)];
    }

    for (int nt = 0; nt < 8; nt++) {
        #pragma unroll
        for (int mt = 0; mt < 2; mt++)
            #pragma unroll
            for (int n8 = 0; n8 < 4; n8++)
                #pragma unroll
                for (int i = 0; i < 4; i++) acc[mt][n8][i] = 0.f;

        const u64* bp = bbase + (size_t)nt * 16 * 16 * 32;
        u64 bc[4], bn[4];
        #pragma unroll
        for (int n8 = 0; n8 < 4; n8++) bc[n8] = __ldg(bp + n8 * 32);

        #pragma unroll
        for (int ks = 0; ks < 16; ks++) {
            if (ks < 15) {
                const u64* np = bp + (ks + 1) * 512;
                #pragma unroll
                for (int n8 = 0; n8 < 4; n8++) bn[n8] = __ldg(np + n8 * 32);
            }
            const uint32_t qoff = (uint32_t)((ks >> 2) * 16384);
            const uint32_t kb = (uint32_t)((ks & 3) * 32);
            uint32_t a[2][4];
            #pragma unroll
            for (int mt = 0; mt < 2; mt++)
                LDSM4(a[mt][0], a[mt][1], a[mt][2], a[mt][3],
                      sb + SM_AHI + qoff + arow[mt] + ((kb + ahalf) ^ arx[mt]));
            #pragma unroll
            for (int mt = 0; mt < 2; mt++)
                #pragma unroll
                for (int n8 = 0; n8 < 4; n8++)
                    MMA16816(acc[mt][n8], a[mt][0], a[mt][1], a[mt][2], a[mt][3],
                             (uint32_t)bc[n8], (uint32_t)(bc[n8] >> 32));
            #pragma unroll
            for (int n8 = 0; n8 < 4; n8++) bc[n8] = bn[n8];
        }

        // ---- epilogue: compute all 32 dists ONCE, fold, guarded append ----
        const int colbase = nt * 128 + warp_n * 32 + (lane & 3) * 2;
        float dl[32];     // [(mt*2+hf)*8 + n8*2 + ci]
        float mnl[4];
        #pragma unroll
        for (int mt = 0; mt < 2; mt++) {
            #pragma unroll
            for (int hf = 0; hf < 2; hf++) {
                const float iq = insqr[mt * 2 + hf];
                float mn = __uint_as_float(0x7F800000u);
                #pragma unroll
                for (int n8 = 0; n8 < 4; n8++) {
                    #pragma unroll
                    for (int ci = 0; ci < 2; ci++) {
                        float tq = iq + s_cbsq[colbase + n8 * 8 + ci];
                        float dist = tq - 2.0f * acc[mt][n8][hf * 2 + ci];
                        dl[(mt * 2 + hf) * 8 + n8 * 2 + ci] = dist;
                        mn = fminf(mn, dist);
                    }
                }
                mnl[mt * 2 + hf] = mn;
                float o1 = __shfl_xor_sync(0xFFFFFFFFu, mn, 1);
                mn = fminf(mn, o1);
                float o2 = __shfl_xor_sync(0xFFFFFFFFu, mn, 2);
                mn = fminf(mn, o2);
                if ((lane & 3) == 0) {
                    int row = warp_m * 32 + mt * 16 + hf * 8 + (lane >> 2);
                    if (mn < __uint_as_float(s_rowmin[row]))
                        atomicMin(&s_rowmin[row], __float_as_uint(mn));
                }
            }
        }
        #pragma unroll
        for (int i = 0; i < 4; i++) {
            const int mt = i >> 1, hf = i & 1;
            const int row = warp_m * 32 + mt * 16 + hf * 8 + (lane >> 2);
            const float thr = __uint_as_float(s_rowmin[row]) + MARGIN;
            if (mnl[i] < thr) {
                #pragma unroll
                for (int j = 0; j < 8; j++) {
                    if (dl[i * 8 + j] < thr) {
                        int pos = atomicAdd(&s_cnt[row], 1);
                        if (pos < MAXCAND)
                            s_cand[row * MAXCAND + pos] =
                                (uint32_t)(colbase + (j >> 1) * 8 + (j & 1));
                    }
                }
            }
        }
    }
    __syncthreads();

    // ---- dump candidates + counts to global (coalesced) ----
    if (t < 128) g_cnt[n0 + t] = s_cnt[t];
    #pragma unroll
    for (int i = 0; i < (128 * MAXCAND) / 512; i++)
        g_cand[(size_t)n0 * MAXCAND + i * 512 + t] = s_cand[i * 512 + t];
}

// ---------------- exact rescore kernel (one candidate per THREAD) ----------------
// Block owns 32 rows. xt rows staged in shared; (row, col) pairs of rows with
// 2 <= cnt <= MAXCAND are packed into a shared queue and processed one per
// thread: cb row via __ldg float4 (L2-resident), dot in the bit-identical
// sequential d=0..255 fp32 fmaf order. cnt==1 short-circuits (the margin is a
// hard bound, so a lone candidate IS the argmin). cnt > MAXCAND (rare/never)
// rows get a block-cooperative full 1024-code scan.
__global__ void __launch_bounds__(256) k_rescore(const float* __restrict__ cb) {
    __shared__ float xt_sh[32 * 257];
    __shared__ uint32_t queue[32 * MAXCAND];
    __shared__ u64 s_best[32];
    __shared__ int s_q, s_nfull;
    __shared__ int s_full[32];

    const int t = threadIdx.x;
    const int n0 = blockIdx.x * 32;

    if (t == 0) { s_q = 0; s_nfull = 0; }
    if (t < 32) s_best[t] = ~0ull;
    __syncthreads();

    // stage 32 xt rows (coalesced float4; stride 257 -> conflict-free reads)
    #pragma unroll
    for (int j = 0; j < 8; j++) {
        int f4 = j * 256 + t;               // 2048 float4
        int row = f4 >> 6, q4 = f4 & 63;
        float4 v = *reinterpret_cast<const float4*>(
            &g_xt[(size_t)(n0 + row) * 256 + q4 * 4]);
        float* dst = &xt_sh[row * 257 + q4 * 4];
        dst[0] = v.x; dst[1] = v.y; dst[2] = v.z; dst[3] = v.w;
    }

    // classify rows + build queue
    if (t < 32) {
        int n = n0 + t;
        int cnt = g_cnt[n];
        if (cnt == 1) {
            int kbest = (int)g_cand[(size_t)n * MAXCAND];
            g_idx[n] = kbest;
            atomicAdd(&g_hist[kbest], 1);
        } else if (cnt <= MAXCAND) {
            int base = atomicAdd(&s_q, cnt);
            for (int i = 0; i < cnt; i++)
                queue[base + i] = ((uint32_t)t << 10) |
                                  g_cand[(size_t)n * MAXCAND + i];
        } else {
            int fi = atomicAdd(&s_nfull, 1);
            s_full[fi] = t;
        }
    }
    __syncthreads();

    // one candidate per thread
    const int qtot = s_q;
    for (int j = t; j < qtot; j += 256) {
        uint32_t e = queue[j];
        int rl = e >> 10, col = (int)(e & 1023);
        const float* xr = &xt_sh[rl * 257];
        const float4* cr4 = reinterpret_cast<const float4*>(cb + (size_t)col * 256);
        float dot = 0.f;
        #pragma unroll 8
        for (int d4 = 0; d4 < 64; d4++) {
            float4 c4 = __ldg(cr4 + d4);
            dot = fmaf(xr[d4 * 4 + 0], c4.x, dot);
            dot = fmaf(xr[d4 * 4 + 1], c4.y, dot);
            dot = fmaf(xr[d4 * 4 + 2], c4.z, dot);
            dot = fmaf(xr[d4 * 4 + 3], c4.w, dot);
        }
        float tq = g_insq[n0 + rl] + g_cbsq[col];
        float dist = tq - 2.0f * dot;
        u64 k = ((u64)__float_as_uint(dist) << 32) | (unsigned)col;
        atomicMin(&s_best[rl], k);
    }

    // full-scan fallback rows (block-cooperative; rare/never)
    const int nfull = s_nfull;
    for (int fi = 0; fi < nfull; fi++) {
        int rl = s_full[fi];
        const float* xr = &xt_sh[rl * 257];
        const float iq = g_insq[n0 + rl];
        u64 best = ~0ull;
        for (int col = t; col < NCODE; col += 256) {
            const float4* cr4 = reinterpret_cast<const float4*>(cb + (size_t)col * 256);
            float dot = 0.f;
            #pragma unroll 8
            for (int d4 = 0; d4 < 64; d4++) {
                float4 c4 = __ldg(cr4 + d4);
                dot = fmaf(xr[d4 * 4 + 0], c4.x, dot);
                dot = fmaf(xr[d4 * 4 + 1], c4.y, dot);
                dot = fmaf(xr[d4 * 4 + 2], c4.z, dot);
                dot = fmaf(xr[d4 * 4 + 3], c4.w, dot);
            }
            float dist = (iq + g_cbsq[col]) - 2.0f * dot;
            u64 k = ((u64)__float_as_uint(dist) << 32) | (unsigned)col;
            if (k < best) best = k;
        }
        if (best != ~0ull) atomicMin(&s_best[rl], best);
    }
    __syncthreads();

    if (t < 32 && s_best[t] != ~0ull) {
        int kbest = (int)(unsigned)(s_best[t] & 0xFFFFFFFFull);
        g_idx[n0 + t] = kbest;
        atomicAdd(&g_hist[kbest], 1);
    }
}

// ---------------- outputs ----------------
__global__ void k_ones(float* __restrict__ enc) {
    int n = blockIdx.x * 256 + threadIdx.x;
    enc[(size_t)n * NCODE + g_idx[n]] = 1.0f;
}

// coalesced xq: block = (b, 32 hw) x 256 d; codebook rows staged in shared.
__global__ void __launch_bounds__(256) k_xq2(const float* __restrict__ x,
                                             const float* __restrict__ cb,
                                             float* __restrict__ outb) {
    __shared__ float cbs[32 * 261];
    __shared__ int idxs[32];
    __shared__ float warpsum[8];
    const int t = threadIdx.x;
    const int b = blockIdx.x >> 7;
    const int hw0 = (blockIdx.x & 127) << 5;
    const int n0 = (b << 12) + hw0;
    if (t < 32) idxs[t] = g_idx[n0 + t];
    __syncthreads();
    #pragma unroll
    for (int j = 0; j < 8; j++) {
        int lin = j * 256 + t;               // 2048 = 32 rows x 64 float4
        int row = lin >> 6, f4 = lin & 63;
        float4 v = *reinterpret_cast<const float4*>(
            &cb[(size_t)idxs[row] * 256 + f4 * 4]);
        float* dst = &cbs[row * 261 + f4 * 4];
        dst[0] = v.x; dst[1] = v.y; dst[2] = v.z; dst[3] = v.w;
    }
    __syncthreads();
    float lsum = 0.f;
    #pragma unroll
    for (int i2 = 0; i2 < 8; i2++) {
        int f4 = i2 * 256 + t;               // 2048 float4 tiles
        int d = f4 >> 3, hw4 = (f4 & 7) * 4;
        size_t gi = (((size_t)b * 256 + d) << 12) + hw0 + hw4;
        float4 xv = *reinterpret_cast<const float4*>(x + gi);
        float q0 = cbs[(hw4 + 0) * 261 + d];
        float q1 = cbs[(hw4 + 1) * 261 + d];
        float q2 = cbs[(hw4 + 2) * 261 + d];
        float q3 = cbs[(hw4 + 3) * 261 + d];
        float d0 = q0 - xv.x, d1 = q1 - xv.y, d2 = q2 - xv.z, d3 = q3 - xv.w;
        lsum += d0 * d0; lsum += d1 * d1; lsum += d2 * d2; lsum += d3 * d3;
        outb[gi]     = xv.x + d0;
        outb[gi + 1] = xv.y + d1;
        outb[gi + 2] = xv.z + d2;
        outb[gi + 3] = xv.w + d3;
    }
    #pragma unroll
    for (int off = 16; off; off >>= 1) lsum += __shfl_down_sync(0xFFFFFFFFu, lsum, off);
    if ((t & 31) == 0) warpsum[t >> 5] = lsum;
    __syncthreads();
    if (t == 0) {
        float s = 0.f;
        #pragma unroll
        for (int ww = 0; ww < 8; ww++) s += warpsum[ww];
        atomicAdd(&g_losssum, (double)s);
    }
}

__global__ void k_fin(float* __restrict__ out_loss, float* __restrict__ out_perp) {
    __shared__ float sred[32];
    int t = threadIdx.x;
    float e_mean = (float)g_hist[t] * (1.0f / 65536.0f);
    float term = e_mean * logf(e_mean + 1e10f);
    #pragma unroll
    for (int off = 16; off; off >>= 1) term += __shfl_down_sync(0xFFFFFFFFu, term, off);
    if ((t & 31) == 0) sred[t >> 5] = term;
    __syncthreads();
    if (t < 32) {
        float v = sred[t];
        #pragma unroll
        for (int off = 16; off; off >>= 1) v += __shfl_down_sync(0xFFFFFFFFu, v, off);
        if (t == 0) {
            if (out_perp) *out_perp = expf(-v);
            if (out_loss) {
                float mse = (float)(g_losssum * (1.0 / 16777216.0));
                *out_loss = mse + 0.25f * mse;
            }
        }
    }
}

extern "C" void kernel_launch(void* const* d_in, const int* in_sizes, int n_in,
                              void* d_out, int out_size) {
    const float* x  = (const float*)d_in[0];
    const float* cb = (const float*)d_in[1];
    if (n_in >= 2 && in_sizes[0] == NCODE * DIM) {
        x  = (const float*)d_in[1];
        cb = (const float*)d_in[0];
    }

    float* out = (float*)d_out;
    float *o_loss = nullptr, *o_xq = nullptr, *o_perp = nullptr, *o_enc = nullptr;
    if (out_size == XELEMS) {
        o_xq = out;
    } else if (out_size == ENCELEMS) {
        o_enc = out;
    } else if (out_size == 2) {
        o_loss = out; o_perp = out + 1;
    } else {
        o_loss = out;
        o_xq   = out + 1;
        o_perp = out + 1 + XELEMS;
        o_enc  = out + 2 + XELEMS;
    }

    cudaFuncSetAttribute(k_mma, cudaFuncAttributeMaxDynamicSharedMemorySize, SM_TOTAL);

    // k_rescore stays the 4th kernel launch (ncu capture lands on launch #4)
    // to verify the packed-queue rework.
    k_prep<<<512, 256>>>(cb);
    k_split_x<<<NROWS / 32, 256>>>(x);
    k_mma<<<NROWS / 128, 512, SM_TOTAL>>>();
    k_rescore<<<NROWS / 32, 256>>>(cb);
    if (o_enc) {
        cudaMemsetAsync(o_enc, 0, (size_t)ENCELEMS * sizeof(float));
        k_ones<<<NROWS / 256, 256>>>(o_enc);
    }
    if (o_xq) k_xq2<<<2048, 256>>>(x, cb, o_xq);
    k_fin<<<1, 1024>>>(o_loss, o_perp);
}